// round 10
// baseline (speedup 1.0000x reference)
#include <cuda_runtime.h>
#include <cuda_fp16.h>
#include <math.h>
#include <stdint.h>

#define NB 64
#define CH 640
#define HH 28
#define WW 28
#define S1 784
#define S2 196
#define HEADS 8
#define DH 64
#define INNER 512
#define EPS 1e-5f
#define ATT_SCALE 0.125f
#define KU (CH / 2)          // 320 u32 (half2) along K
#define PW 30                // padded dwconv smem plane width

// fp16 attention tiling (validated R9)
#define NPAD 208
#define QS2  36
#define KS2  232
#define VS2  72
#define SS   228
#define RS   68
#define KPJ  104

// ---- static scratch ----
__device__ uint32_t g_dqh [NB * KU * S1];
__device__ uint32_t g_dkvh[NB * KU * S2];
__device__ uint32_t g_xh  [NB * KU * S1];
__device__ uint32_t g_wqh [INNER * KU];
__device__ uint32_t g_wkvh[2 * INNER * KU];
__device__ uint32_t g_wdsh[DH * KU];
__device__ float g_q  [NB * INNER * S1];
__device__ float g_kv [NB * 2 * INNER * S2];
__device__ float g_res[NB * DH * S1];

// ---------------------------------------------------------------------------
__device__ __forceinline__ uint32_t h2_u32(float a, float b) {
    __half2 h = __floats2half2_rn(a, b);
    return *reinterpret_cast<uint32_t*>(&h);
}

// pack weights: fp32 [M][K] -> u32 half2 [M][K/2]
__global__ void pack_w_kernel(const float* __restrict__ in,
                              uint32_t* __restrict__ out, int n)
{
    int i = blockIdx.x * blockDim.x + threadIdx.x;
    if (i >= n) return;
    float2 v = ((const float2*)in)[i];
    out[i] = h2_u32(v.x, v.y);
}

// pack x: fp32 [b][C][S1] -> u32 [b][C/2][S1], 2 s-positions per thread
__global__ void pack_x_kernel(const float* __restrict__ x,
                              uint32_t* __restrict__ out, int total2)
{
    int i = blockIdx.x * blockDim.x + threadIdx.x;
    if (i >= total2) return;
    int s2 = i % (S1 / 2);
    int t  = i / (S1 / 2);
    int cp = t % KU;
    int b  = t / KU;
    int s  = 2 * s2;
    const float* xp = x + ((size_t)b * CH + 2 * cp) * S1 + s;
    float2 a = *(const float2*)xp;
    float2 c = *(const float2*)(xp + S1);
    uint2 r;
    r.x = h2_u32(a.x, c.x);
    r.y = h2_u32(a.y, c.y);
    *(uint2*)&out[((size_t)b * KU + cp) * S1 + s] = r;
}

// ---------------------------------------------------------------------------
// Depthwise 3x3 conv + BN, smem-staged: one block per (b, channel-pair).
// Input plane (28x28 x2ch) staged into zero-padded 30x30 halo; outputs
// computed branch-free. Output u32 half2 [b][C/2][Ho*Wo].
// ---------------------------------------------------------------------------
__global__ void __launch_bounds__(256)
dwconv_smem_kernel(const float* __restrict__ x,
                   const float* __restrict__ w,
                   const float* __restrict__ bg,
                   const float* __restrict__ bb,
                   const float* __restrict__ bm,
                   const float* __restrict__ bv,
                   uint32_t* __restrict__ out,
                   int stride, int Ho, int Wo)
{
    __shared__ float xs0[PW * PW];
    __shared__ float xs1[PW * PW];

    const int blk = blockIdx.x;
    const int cp  = blk % KU;
    const int b   = blk / KU;
    const int c0  = 2 * cp;
    const int tid = threadIdx.x;

    const float* xp0 = x + ((size_t)b * CH + c0) * S1;
    const float* xp1 = xp0 + S1;

    for (int i = tid; i < PW * PW; i += 256) { xs0[i] = 0.f; xs1[i] = 0.f; }
    __syncthreads();
    for (int i = tid; i < S1; i += 256) {
        int yy = i / WW, xx = i - yy * WW;
        int d = (yy + 1) * PW + xx + 1;
        xs0[d] = xp0[i];
        xs1[d] = xp1[i];
    }

    float w0[9], w1[9];
#pragma unroll
    for (int k = 0; k < 9; k++) {
        w0[k] = w[c0 * 9 + k];
        w1[k] = w[c0 * 9 + 9 + k];
    }
    const float i0 = bg[c0] * rsqrtf(bv[c0] + EPS);
    const float i1 = bg[c0 + 1] * rsqrtf(bv[c0 + 1] + EPS);
    const float s0 = bb[c0] - bm[c0] * i0;
    const float s1 = bb[c0 + 1] - bm[c0 + 1] * i1;
    __syncthreads();

    const int total = Ho * Wo;
    uint32_t* op = out + (size_t)((size_t)b * KU + cp) * total;
    for (int o = tid; o < total; o += 256) {
        int yo = o / Wo, xo = o - yo * Wo;
        int base = (yo * stride) * PW + xo * stride;
        float a0 = 0.f, a1 = 0.f;
#pragma unroll
        for (int dy = 0; dy < 3; dy++)
#pragma unroll
            for (int dx = 0; dx < 3; dx++) {
                int off = base + dy * PW + dx;
                a0 += xs0[off] * w0[dy * 3 + dx];
                a1 += xs1[off] * w1[dy * 3 + dx];
            }
        op[o] = h2_u32(a0 * i0 + s0, a1 * i1 + s1);
    }
}

// ---------------------------------------------------------------------------
// fp16 mma.sync m16n8k16, fp32 accumulate
// ---------------------------------------------------------------------------
__device__ __forceinline__ void mma_f16(float* c, const unsigned int* a,
                                        const unsigned int* b)
{
    asm volatile(
        "mma.sync.aligned.m16n8k16.row.col.f32.f16.f16.f32 "
        "{%0,%1,%2,%3}, {%4,%5,%6,%7}, {%8,%9}, {%0,%1,%2,%3};\n"
        : "+f"(c[0]), "+f"(c[1]), "+f"(c[2]), "+f"(c[3])
        : "r"(a[0]), "r"(a[1]), "r"(a[2]), "r"(a[3]), "r"(b[0]), "r"(b[1]));
}

__device__ __forceinline__ void cp_async16(uint32_t* smem_dst, const uint32_t* gsrc,
                                           bool valid)
{
    unsigned int saddr = (unsigned int)__cvta_generic_to_shared(smem_dst);
    int sz = valid ? 16 : 0;
    asm volatile("cp.async.ca.shared.global [%0], [%1], 16, %2;\n"
                 :: "r"(saddr), "l"(gsrc), "r"(sz));
}
#define CP_COMMIT() asm volatile("cp.async.commit_group;\n" ::: "memory")
#define CP_WAIT2()  asm volatile("cp.async.wait_group 2;\n" ::: "memory")

// ---------------------------------------------------------------------------
// fp16 cp.async 4-stage pipelined GEMM (validated R8, unchanged)
// ---------------------------------------------------------------------------
#define PA 20
#define PB 136
#define STAGES 4
#define ASTG (128 * PA)
#define BSTG (16 * PB)

__global__ void __launch_bounds__(256, 2)
gemm_f16_kernel(const uint32_t* __restrict__ A,
                const uint32_t* __restrict__ Bmat,
                float* __restrict__ C,
                int M, int N,
                const float* __restrict__ bg,
                const float* __restrict__ bb,
                const float* __restrict__ bm,
                const float* __restrict__ bv)
{
    extern __shared__ __align__(16) uint32_t smem[];
    uint32_t* As = smem;
    uint32_t* Bs = smem + STAGES * ASTG;

    const int tid  = threadIdx.x;
    const int lane = tid & 31;
    const int wid  = tid >> 5;
    const int wm   = (wid >> 2) * 64;
    const int wn   = (wid & 3) * 32;
    const int g    = lane >> 2;
    const int t    = lane & 3;

    const int row0  = blockIdx.y * 128;
    const int col0  = blockIdx.x * 128;
    const int batch = blockIdx.z;
    const uint32_t* Bb = Bmat + (size_t)batch * KU * N;
    float*          Cb = C    + (size_t)batch * M * N;

    const int ar  = tid >> 1;
    const int ac  = (tid & 1) * 8;
    const int br  = tid >> 4;
    const int bc  = (tid & 15) * 8;
    const bool aok = (row0 + ar) < M;
    const bool bok = (col0 + bc) < N;

    const uint32_t* ap = A  + (size_t)(aok ? (row0 + ar) : 0) * KU + ac;
    const uint32_t* bp = Bb + (size_t)br * N + (bok ? (col0 + bc) : 0);

    float c[4][4][4];
#pragma unroll
    for (int i = 0; i < 4; i++)
#pragma unroll
        for (int j = 0; j < 4; j++)
#pragma unroll
            for (int l = 0; l < 4; l++) c[i][j][l] = 0.f;

    const int NKT = KU / 16;  // 20

#define ISSUE(kt_)                                                              \
    do {                                                                        \
        int s_ = (kt_) & (STAGES - 1);                                          \
        int k0_ = (kt_) * 16;                                                   \
        cp_async16(&As[s_ * ASTG + ar * PA + ac],     ap + k0_,     aok);       \
        cp_async16(&As[s_ * ASTG + ar * PA + ac + 4], ap + k0_ + 4, aok);       \
        cp_async16(&Bs[s_ * BSTG + br * PB + bc],     bp + (size_t)k0_ * N,     bok); \
        cp_async16(&Bs[s_ * BSTG + br * PB + bc + 4], bp + (size_t)k0_ * N + 4, bok); \
    } while (0)

#pragma unroll
    for (int kt = 0; kt < STAGES - 1; kt++) { ISSUE(kt); CP_COMMIT(); }

    for (int kt = 0; kt < NKT; kt++) {
        CP_WAIT2();
        __syncthreads();

        const uint32_t* Asu = &As[(kt & (STAGES - 1)) * ASTG];
        const uint32_t* Bsu = &Bs[(kt & (STAGES - 1)) * BSTG];
#pragma unroll
        for (int ks = 0; ks < 2; ks++) {
            unsigned int af[4][4], bf[4][2];
#pragma unroll
            for (int mt = 0; mt < 4; mt++) {
                int mb = wm + mt * 16;
                af[mt][0] = Asu[(mb + g    ) * PA + ks * 8 + t];
                af[mt][1] = Asu[(mb + g + 8) * PA + ks * 8 + t];
                af[mt][2] = Asu[(mb + g    ) * PA + ks * 8 + t + 4];
                af[mt][3] = Asu[(mb + g + 8) * PA + ks * 8 + t + 4];
            }
#pragma unroll
            for (int nt = 0; nt < 4; nt++) {
                int nb = wn + nt * 8 + g;
                bf[nt][0] = Bsu[(ks * 8 + t    ) * PB + nb];
                bf[nt][1] = Bsu[(ks * 8 + t + 4) * PB + nb];
            }
#pragma unroll
            for (int mt = 0; mt < 4; mt++)
#pragma unroll
                for (int nt = 0; nt < 4; nt++)
                    mma_f16(c[mt][nt], af[mt], bf[nt]);
        }

        if (kt + STAGES - 1 < NKT) ISSUE(kt + STAGES - 1);
        CP_COMMIT();
    }
#undef ISSUE

#pragma unroll
    for (int mt = 0; mt < 4; mt++) {
        int r0 = row0 + wm + mt * 16 + g;
        int r1 = r0 + 8;
        float sc0 = 1.f, sh0 = 0.f, sc1 = 1.f, sh1 = 0.f;
        if (bg) {
            if (r0 < M) {
                float inv = bg[r0] * rsqrtf(bv[r0] + EPS);
                sc0 = inv; sh0 = bb[r0] - bm[r0] * inv;
            }
            if (r1 < M) {
                float inv = bg[r1] * rsqrtf(bv[r1] + EPS);
                sc1 = inv; sh1 = bb[r1] - bm[r1] * inv;
            }
        }
#pragma unroll
        for (int nt = 0; nt < 4; nt++) {
            int cc = col0 + wn + nt * 8 + 2 * t;
            if (cc < N) {
                if (r0 < M)
                    *(float2*)&Cb[(size_t)r0 * N + cc] =
                        make_float2(c[mt][nt][0] * sc0 + sh0, c[mt][nt][1] * sc0 + sh0);
                if (r1 < M)
                    *(float2*)&Cb[(size_t)r1 * N + cc] =
                        make_float2(c[mt][nt][2] * sc1 + sh1, c[mt][nt][3] * sc1 + sh1);
            }
        }
    }
}

// ---------------------------------------------------------------------------
// fp16 tensor-core attention + residual + LN + spatial mean (validated R9)
// ---------------------------------------------------------------------------
__global__ void __launch_bounds__(256, 1)
attn_f16_kernel(const float* __restrict__ qb,
                const float* __restrict__ kvb,
                const float* __restrict__ resb,
                const float* __restrict__ lng,
                const float* __restrict__ lnb,
                float* __restrict__ out)
{
    extern __shared__ uint32_t smu[];
    uint32_t* Qsm = smu;                    // [64][QS2]
    uint32_t* Ksm = Qsm + 64 * QS2;         // [32][KS2]
    uint32_t* Vsm = Ksm + 32 * KS2;         // [KPJ][VS2]
    float*    Ssm = (float*)(Vsm + KPJ * VS2);  // [64][SS]
    float*    Rsm = Ssm + 64 * SS;          // [64][RS]
    float*    rowZ = Rsm + 64 * RS;         // [64]
    float*    accs = rowZ + 64;             // [8][64]

    const int bh   = blockIdx.x;
    const int b    = bh >> 3, h = bh & 7;
    const int tid  = threadIdx.x;
    const int wid  = tid >> 5;
    const int lane = tid & 31;
    const int g    = lane >> 2;
    const int t    = lane & 3;
    const int wm   = (wid >> 1) * 16;
    const int wnS  = (wid & 1) * 104;
    const int wnO  = (wid & 1) * 32;

    const float* kbase = kvb + ((size_t)b * (2 * INNER) + h * DH) * S2;
    const float* vbase = kbase + (size_t)INNER * S2;
    const float* qbase = qb   + ((size_t)b * INNER + h * DH) * S1;
    const float* rbase = resb + (size_t)b * DH * S1;

    for (int i = tid; i < 32 * NPAD; i += 256) {
        int kp = i / NPAD, j = i - kp * NPAD;
        float a = 0.f, c = 0.f;
        if (j < S2) {
            a = kbase[(size_t)(2 * kp)     * S2 + j];
            c = kbase[(size_t)(2 * kp + 1) * S2 + j];
        }
        Ksm[kp * KS2 + j] = h2_u32(a, c);
    }
    for (int i = tid; i < KPJ * DH; i += 256) {
        int kpj = i % KPJ, d = i / KPJ;
        float a = 0.f, c = 0.f;
        if (2 * kpj < S2) {
            const float* vp = vbase + (size_t)d * S2 + 2 * kpj;
            a = vp[0]; c = vp[1];
        }
        Vsm[kpj * VS2 + d] = h2_u32(a, c);
    }
    for (int i = tid; i < 8 * 64; i += 256) accs[i] = 0.f;

    const float lg0 = lng[h * DH + lane], lg1 = lng[h * DH + lane + 32];
    const float lb0 = lnb[h * DH + lane], lb1 = lnb[h * DH + lane + 32];

    for (int s0 = 0; s0 < S1; s0 += 64) {
        const int len = min(64, S1 - s0);
        __syncthreads();

        for (int i = tid; i < 64 * 32; i += 256) {
            int r = i & 63, kp = i >> 6;
            float a = 0.f, c = 0.f;
            if (r < len) {
                const float* qp = qbase + (size_t)(2 * kp) * S1 + s0 + r;
                a = qp[0]; c = qp[S1];
            }
            Qsm[r * QS2 + kp] = h2_u32(a, c);
        }
        __syncthreads();

        {
            float c[13][4];
#pragma unroll
            for (int nt = 0; nt < 13; nt++)
#pragma unroll
                for (int l = 0; l < 4; l++) c[nt][l] = 0.f;
#pragma unroll
            for (int ks = 0; ks < 4; ks++) {
                unsigned int af[4], bf[13][2];
                af[0] = Qsm[(wm + g    ) * QS2 + ks * 8 + t];
                af[1] = Qsm[(wm + g + 8) * QS2 + ks * 8 + t];
                af[2] = Qsm[(wm + g    ) * QS2 + ks * 8 + t + 4];
                af[3] = Qsm[(wm + g + 8) * QS2 + ks * 8 + t + 4];
#pragma unroll
                for (int nt = 0; nt < 13; nt++) {
                    int nb = wnS + nt * 8 + g;
                    bf[nt][0] = Ksm[(ks * 8 + t    ) * KS2 + nb];
                    bf[nt][1] = Ksm[(ks * 8 + t + 4) * KS2 + nb];
                }
#pragma unroll
                for (int nt = 0; nt < 13; nt++)
                    mma_f16(c[nt], af, bf[nt]);
            }
#pragma unroll
            for (int nt = 0; nt < 13; nt++) {
                int col = wnS + nt * 8 + 2 * t;
                *(float2*)&Ssm[(wm + g    ) * SS + col] =
                    make_float2(c[nt][0] * ATT_SCALE, c[nt][1] * ATT_SCALE);
                *(float2*)&Ssm[(wm + g + 8) * SS + col] =
                    make_float2(c[nt][2] * ATT_SCALE, c[nt][3] * ATT_SCALE);
            }
        }
        __syncthreads();

        if (tid < 64) {
            int r = tid;
            if (r < len) {
                float* Srow = &Ssm[r * SS];
                uint32_t* Prow = (uint32_t*)Srow;
                float mx = -1e30f;
                for (int j = 0; j < S2; j++) mx = fmaxf(mx, Srow[j]);
                float Z = 0.f;
                for (int kp = 0; kp < 98; kp++) {
                    float e0 = __expf(Srow[2 * kp]     - mx);
                    float e1 = __expf(Srow[2 * kp + 1] - mx);
                    Z += e0 + e1;
                    Prow[kp] = h2_u32(e0, e1);
                }
#pragma unroll
                for (int kp = 98; kp < KPJ; kp++) Prow[kp] = 0u;
                rowZ[r] = Z;
            }
        } else {
            for (int i = tid - 64; i < 64 * 64; i += 192) {
                int d = i >> 6, r = i & 63;
                if (r < len) Rsm[r * RS + d] = rbase[(size_t)d * S1 + s0 + r];
            }
        }
        __syncthreads();

        {
            float o[4][4];
#pragma unroll
            for (int nt = 0; nt < 4; nt++)
#pragma unroll
                for (int l = 0; l < 4; l++) o[nt][l] = 0.f;

            const uint32_t* Ssu = (const uint32_t*)Ssm;
#pragma unroll
            for (int ks = 0; ks < 13; ks++) {
                unsigned int af[4], bf[4][2];
                af[0] = Ssu[(wm + g    ) * SS + ks * 8 + t];
                af[1] = Ssu[(wm + g + 8) * SS + ks * 8 + t];
                af[2] = Ssu[(wm + g    ) * SS + ks * 8 + t + 4];
                af[3] = Ssu[(wm + g + 8) * SS + ks * 8 + t + 4];
#pragma unroll
                for (int nt = 0; nt < 4; nt++) {
                    int nb = wnO + nt * 8 + g;
                    bf[nt][0] = Vsm[(ks * 8 + t    ) * VS2 + nb];
                    bf[nt][1] = Vsm[(ks * 8 + t + 4) * VS2 + nb];
                }
#pragma unroll
                for (int nt = 0; nt < 4; nt++)
                    mma_f16(o[nt], af, bf[nt]);
            }
            int r0 = wm + g, r1 = wm + g + 8;
            float rz0 = 1.f / rowZ[r0], rz1 = 1.f / rowZ[r1];
#pragma unroll
            for (int nt = 0; nt < 4; nt++) {
                int d0 = wnO + nt * 8 + 2 * t;
                Rsm[r0 * RS + d0]     += o[nt][0] * rz0;
                Rsm[r0 * RS + d0 + 1] += o[nt][1] * rz0;
                Rsm[r1 * RS + d0]     += o[nt][2] * rz1;
                Rsm[r1 * RS + d0 + 1] += o[nt][3] * rz1;
            }
        }
        __syncthreads();

        for (int r = wid; r < len; r += 8) {
            float x0 = Rsm[r * RS + lane], x1 = Rsm[r * RS + lane + 32];
            float sum = x0 + x1, sq = x0 * x0 + x1 * x1;
#pragma unroll
            for (int o2 = 16; o2 > 0; o2 >>= 1) {
                sum += __shfl_xor_sync(0xffffffffu, sum, o2);
                sq  += __shfl_xor_sync(0xffffffffu, sq, o2);
            }
            float mean = sum * (1.f / 64.f);
            float var  = fmaxf(sq * (1.f / 64.f) - mean * mean, 0.f);
            float rs   = 1.f / (sqrtf(var) + EPS);
            accs[wid * 64 + lane]      += (x0 - mean) * rs * lg0 + lb0;
            accs[wid * 64 + lane + 32] += (x1 - mean) * rs * lg1 + lb1;
        }
    }
    __syncthreads();
    if (tid < 64) {
        float s = 0.f;
#pragma unroll
        for (int w2 = 0; w2 < 8; w2++) s += accs[w2 * 64 + tid];
        out[((size_t)b * HEADS + h) * DH + tid] = s * (1.f / 784.f);
    }
}

// ---------------------------------------------------------------------------
extern "C" void kernel_launch(void* const* d_in, const int* in_sizes, int n_in,
                              void* d_out, int out_size)
{
    const float* x      = (const float*)d_in[0];
    const float* w_dwq  = (const float*)d_in[1];
    const float* w_pwq  = (const float*)d_in[2];
    const float* w_dwkv = (const float*)d_in[3];
    const float* w_pwkv = (const float*)d_in[4];
    const float* w_ds   = (const float*)d_in[5];
    const float* ln_g   = (const float*)d_in[6];
    const float* ln_b   = (const float*)d_in[7];
    const float* bnq_g  = (const float*)d_in[8];
    const float* bnq_b  = (const float*)d_in[9];
    const float* bnq_m  = (const float*)d_in[10];
    const float* bnq_v  = (const float*)d_in[11];
    const float* bnkv_g = (const float*)d_in[12];
    const float* bnkv_b = (const float*)d_in[13];
    const float* bnkv_m = (const float*)d_in[14];
    const float* bnkv_v = (const float*)d_in[15];
    const float* bnds_g = (const float*)d_in[16];
    const float* bnds_b = (const float*)d_in[17];
    const float* bnds_m = (const float*)d_in[18];
    const float* bnds_v = (const float*)d_in[19];
    float* out = (float*)d_out;

    void *p_dqh, *p_dkvh, *p_xh, *p_wqh, *p_wkvh, *p_wdsh, *p_q, *p_kv, *p_res;
    cudaGetSymbolAddress(&p_dqh,  g_dqh);
    cudaGetSymbolAddress(&p_dkvh, g_dkvh);
    cudaGetSymbolAddress(&p_xh,   g_xh);
    cudaGetSymbolAddress(&p_wqh,  g_wqh);
    cudaGetSymbolAddress(&p_wkvh, g_wkvh);
    cudaGetSymbolAddress(&p_wdsh, g_wdsh);
    cudaGetSymbolAddress(&p_q,    g_q);
    cudaGetSymbolAddress(&p_kv,   g_kv);
    cudaGetSymbolAddress(&p_res,  g_res);

    const size_t gemm_smem = (size_t)STAGES * (ASTG + BSTG) * sizeof(uint32_t);
    cudaFuncSetAttribute(gemm_f16_kernel,
                         cudaFuncAttributeMaxDynamicSharedMemorySize, (int)gemm_smem);

    // (1) pack q weights
    { int n = INNER * KU; pack_w_kernel<<<(n + 255) / 256, 256>>>(w_pwq, (uint32_t*)p_wqh, n); }
    // (2) dwconv q + BN + pack (smem-staged)
    dwconv_smem_kernel<<<NB * KU, 256>>>(
        x, w_dwq, bnq_g, bnq_b, bnq_m, bnq_v, (uint32_t*)p_dqh, 1, HH, WW);
    // (3) pack kv weights
    { int n = 2 * INNER * KU; pack_w_kernel<<<(n + 255) / 256, 256>>>(w_pwkv, (uint32_t*)p_wkvh, n); }
    // (4) q GEMM
    {
        dim3 grid((S1 + 127) / 128, INNER / 128, NB);
        gemm_f16_kernel<<<grid, 256, gemm_smem>>>(
            (const uint32_t*)p_wqh, (const uint32_t*)p_dqh, (float*)p_q,
            INNER, S1, nullptr, nullptr, nullptr, nullptr);
    }
    // (5) dwconv kv + BN + pack (smem-staged)
    dwconv_smem_kernel<<<NB * KU, 256>>>(
        x, w_dwkv, bnkv_g, bnkv_b, bnkv_m, bnkv_v, (uint32_t*)p_dkvh, 2, 14, 14);
    // (6) pack ds weights, (7) pack x
    { int n = DH * KU; pack_w_kernel<<<(n + 255) / 256, 256>>>(w_ds, (uint32_t*)p_wdsh, n); }
    { int t2 = NB * KU * (S1 / 2); pack_x_kernel<<<(t2 + 255) / 256, 256>>>(x, (uint32_t*)p_xh, t2); }
    // (8) kv GEMM
    {
        dim3 grid((S2 + 127) / 128, (2 * INNER) / 128, NB);
        gemm_f16_kernel<<<grid, 256, gemm_smem>>>(
            (const uint32_t*)p_wkvh, (const uint32_t*)p_dkvh, (float*)p_kv,
            2 * INNER, S2, nullptr, nullptr, nullptr, nullptr);
    }
    // (9) residual GEMM (+BN)
    {
        dim3 grid((S1 + 127) / 128, 1, NB);
        gemm_f16_kernel<<<grid, 256, gemm_smem>>>(
            (const uint32_t*)p_wdsh, (const uint32_t*)p_xh, (float*)p_res,
            DH, S1, bnds_g, bnds_b, bnds_m, bnds_v);
    }
    // (10) fp16 attention + residual + LN + mean
    {
        size_t smem = (size_t)(64 * QS2 + 32 * KS2 + KPJ * VS2 +
                               64 * SS + 64 * RS + 64 + 8 * 64) * 4;
        cudaFuncSetAttribute(attn_f16_kernel,
                             cudaFuncAttributeMaxDynamicSharedMemorySize, (int)smem);
        attn_f16_kernel<<<NB * HEADS, 256, smem>>>(
            (const float*)p_q, (const float*)p_kv, (const float*)p_res,
            ln_g, ln_b, out);
    }
}

// round 11
// speedup vs baseline: 1.0998x; 1.0998x over previous
#include <cuda_runtime.h>
#include <cuda_fp16.h>
#include <math.h>
#include <stdint.h>

#define NB 64
#define CH 640
#define HH 28
#define WW 28
#define S1 784
#define S2 196
#define HEADS 8
#define DH 64
#define INNER 512
#define EPS 1e-5f
#define ATT_SCALE 0.125f
#define KU (CH / 2)
#define PW 30

// fp16 attention tiling
#define NPAD 208
#define QS2  36
#define KS2  232
#define VS2  72
#define SS   228
#define PS   108   // P (half2) row stride: {g*12+t} mod 32 covers all banks
#define RS   68
#define KPJ  104

// ---- static scratch ----
__device__ uint32_t g_dqh [NB * KU * S1];
__device__ uint32_t g_dkvh[NB * KU * S2];
__device__ uint32_t g_xh  [NB * KU * S1];
__device__ uint32_t g_wqh [INNER * KU];
__device__ uint32_t g_wkvh[2 * INNER * KU];
__device__ uint32_t g_wdsh[DH * KU];
__device__ float g_q  [NB * INNER * S1];
__device__ float g_kv [NB * 2 * INNER * S2];
__device__ float g_res[NB * DH * S1];

// ---------------------------------------------------------------------------
__device__ __forceinline__ uint32_t h2_u32(float a, float b) {
    __half2 h = __floats2half2_rn(a, b);
    return *reinterpret_cast<uint32_t*>(&h);
}

__global__ void pack_w_kernel(const float* __restrict__ in,
                              uint32_t* __restrict__ out, int n)
{
    int i = blockIdx.x * blockDim.x + threadIdx.x;
    if (i >= n) return;
    float2 v = ((const float2*)in)[i];
    out[i] = h2_u32(v.x, v.y);
}

__global__ void pack_x_kernel(const float* __restrict__ x,
                              uint32_t* __restrict__ out, int total2)
{
    int i = blockIdx.x * blockDim.x + threadIdx.x;
    if (i >= total2) return;
    int s2 = i % (S1 / 2);
    int t  = i / (S1 / 2);
    int cp = t % KU;
    int b  = t / KU;
    int s  = 2 * s2;
    const float* xp = x + ((size_t)b * CH + 2 * cp) * S1 + s;
    float2 a = *(const float2*)xp;
    float2 c = *(const float2*)(xp + S1);
    uint2 r;
    r.x = h2_u32(a.x, c.x);
    r.y = h2_u32(a.y, c.y);
    *(uint2*)&out[((size_t)b * KU + cp) * S1 + s] = r;
}

// ---------------------------------------------------------------------------
// Depthwise 3x3 conv + BN, smem-staged (validated R10)
// ---------------------------------------------------------------------------
__global__ void __launch_bounds__(256)
dwconv_smem_kernel(const float* __restrict__ x,
                   const float* __restrict__ w,
                   const float* __restrict__ bg,
                   const float* __restrict__ bb,
                   const float* __restrict__ bm,
                   const float* __restrict__ bv,
                   uint32_t* __restrict__ out,
                   int stride, int Ho, int Wo)
{
    __shared__ float xs0[PW * PW];
    __shared__ float xs1[PW * PW];

    const int blk = blockIdx.x;
    const int cp  = blk % KU;
    const int b   = blk / KU;
    const int c0  = 2 * cp;
    const int tid = threadIdx.x;

    const float* xp0 = x + ((size_t)b * CH + c0) * S1;
    const float* xp1 = xp0 + S1;

    for (int i = tid; i < PW * PW; i += 256) { xs0[i] = 0.f; xs1[i] = 0.f; }
    __syncthreads();
    for (int i = tid; i < S1; i += 256) {
        int yy = i / WW, xx = i - yy * WW;
        int d = (yy + 1) * PW + xx + 1;
        xs0[d] = xp0[i];
        xs1[d] = xp1[i];
    }

    float w0[9], w1[9];
#pragma unroll
    for (int k = 0; k < 9; k++) {
        w0[k] = w[c0 * 9 + k];
        w1[k] = w[c0 * 9 + 9 + k];
    }
    const float i0 = bg[c0] * rsqrtf(bv[c0] + EPS);
    const float i1 = bg[c0 + 1] * rsqrtf(bv[c0 + 1] + EPS);
    const float s0 = bb[c0] - bm[c0] * i0;
    const float s1 = bb[c0 + 1] - bm[c0 + 1] * i1;
    __syncthreads();

    const int total = Ho * Wo;
    uint32_t* op = out + (size_t)((size_t)b * KU + cp) * total;
    for (int o = tid; o < total; o += 256) {
        int yo = o / Wo, xo = o - yo * Wo;
        int base = (yo * stride) * PW + xo * stride;
        float a0 = 0.f, a1 = 0.f;
#pragma unroll
        for (int dy = 0; dy < 3; dy++)
#pragma unroll
            for (int dx = 0; dx < 3; dx++) {
                int off = base + dy * PW + dx;
                a0 += xs0[off] * w0[dy * 3 + dx];
                a1 += xs1[off] * w1[dy * 3 + dx];
            }
        op[o] = h2_u32(a0 * i0 + s0, a1 * i1 + s1);
    }
}

// ---------------------------------------------------------------------------
__device__ __forceinline__ void mma_f16(float* c, const unsigned int* a,
                                        const unsigned int* b)
{
    asm volatile(
        "mma.sync.aligned.m16n8k16.row.col.f32.f16.f16.f32 "
        "{%0,%1,%2,%3}, {%4,%5,%6,%7}, {%8,%9}, {%0,%1,%2,%3};\n"
        : "+f"(c[0]), "+f"(c[1]), "+f"(c[2]), "+f"(c[3])
        : "r"(a[0]), "r"(a[1]), "r"(a[2]), "r"(a[3]), "r"(b[0]), "r"(b[1]));
}

__device__ __forceinline__ void cp_async16(uint32_t* smem_dst, const uint32_t* gsrc,
                                           bool valid)
{
    unsigned int saddr = (unsigned int)__cvta_generic_to_shared(smem_dst);
    int sz = valid ? 16 : 0;
    asm volatile("cp.async.ca.shared.global [%0], [%1], 16, %2;\n"
                 :: "r"(saddr), "l"(gsrc), "r"(sz));
}
#define CP_COMMIT() asm volatile("cp.async.commit_group;\n" ::: "memory")
#define CP_WAIT2()  asm volatile("cp.async.wait_group 2;\n" ::: "memory")

// ---------------------------------------------------------------------------
// fp16 cp.async 4-stage pipelined GEMM (validated R8, unchanged)
// ---------------------------------------------------------------------------
#define PA 20
#define PB 136
#define STAGES 4
#define ASTG (128 * PA)
#define BSTG (16 * PB)

__global__ void __launch_bounds__(256, 2)
gemm_f16_kernel(const uint32_t* __restrict__ A,
                const uint32_t* __restrict__ Bmat,
                float* __restrict__ C,
                int M, int N,
                const float* __restrict__ bg,
                const float* __restrict__ bb,
                const float* __restrict__ bm,
                const float* __restrict__ bv)
{
    extern __shared__ __align__(16) uint32_t smem[];
    uint32_t* As = smem;
    uint32_t* Bs = smem + STAGES * ASTG;

    const int tid  = threadIdx.x;
    const int lane = tid & 31;
    const int wid  = tid >> 5;
    const int wm   = (wid >> 2) * 64;
    const int wn   = (wid & 3) * 32;
    const int g    = lane >> 2;
    const int t    = lane & 3;

    const int row0  = blockIdx.y * 128;
    const int col0  = blockIdx.x * 128;
    const int batch = blockIdx.z;
    const uint32_t* Bb = Bmat + (size_t)batch * KU * N;
    float*          Cb = C    + (size_t)batch * M * N;

    const int ar  = tid >> 1;
    const int ac  = (tid & 1) * 8;
    const int br  = tid >> 4;
    const int bc  = (tid & 15) * 8;
    const bool aok = (row0 + ar) < M;
    const bool bok = (col0 + bc) < N;

    const uint32_t* ap = A  + (size_t)(aok ? (row0 + ar) : 0) * KU + ac;
    const uint32_t* bp = Bb + (size_t)br * N + (bok ? (col0 + bc) : 0);

    float c[4][4][4];
#pragma unroll
    for (int i = 0; i < 4; i++)
#pragma unroll
        for (int j = 0; j < 4; j++)
#pragma unroll
            for (int l = 0; l < 4; l++) c[i][j][l] = 0.f;

    const int NKT = KU / 16;

#define ISSUE(kt_)                                                              \
    do {                                                                        \
        int s_ = (kt_) & (STAGES - 1);                                          \
        int k0_ = (kt_) * 16;                                                   \
        cp_async16(&As[s_ * ASTG + ar * PA + ac],     ap + k0_,     aok);       \
        cp_async16(&As[s_ * ASTG + ar * PA + ac + 4], ap + k0_ + 4, aok);       \
        cp_async16(&Bs[s_ * BSTG + br * PB + bc],     bp + (size_t)k0_ * N,     bok); \
        cp_async16(&Bs[s_ * BSTG + br * PB + bc + 4], bp + (size_t)k0_ * N + 4, bok); \
    } while (0)

#pragma unroll
    for (int kt = 0; kt < STAGES - 1; kt++) { ISSUE(kt); CP_COMMIT(); }

    for (int kt = 0; kt < NKT; kt++) {
        CP_WAIT2();
        __syncthreads();

        const uint32_t* Asu = &As[(kt & (STAGES - 1)) * ASTG];
        const uint32_t* Bsu = &Bs[(kt & (STAGES - 1)) * BSTG];
#pragma unroll
        for (int ks = 0; ks < 2; ks++) {
            unsigned int af[4][4], bf[4][2];
#pragma unroll
            for (int mt = 0; mt < 4; mt++) {
                int mb = wm + mt * 16;
                af[mt][0] = Asu[(mb + g    ) * PA + ks * 8 + t];
                af[mt][1] = Asu[(mb + g + 8) * PA + ks * 8 + t];
                af[mt][2] = Asu[(mb + g    ) * PA + ks * 8 + t + 4];
                af[mt][3] = Asu[(mb + g + 8) * PA + ks * 8 + t + 4];
            }
#pragma unroll
            for (int nt = 0; nt < 4; nt++) {
                int nb = wn + nt * 8 + g;
                bf[nt][0] = Bsu[(ks * 8 + t    ) * PB + nb];
                bf[nt][1] = Bsu[(ks * 8 + t + 4) * PB + nb];
            }
#pragma unroll
            for (int mt = 0; mt < 4; mt++)
#pragma unroll
                for (int nt = 0; nt < 4; nt++)
                    mma_f16(c[mt][nt], af[mt], bf[nt]);
        }

        if (kt + STAGES - 1 < NKT) ISSUE(kt + STAGES - 1);
        CP_COMMIT();
    }
#undef ISSUE

#pragma unroll
    for (int mt = 0; mt < 4; mt++) {
        int r0 = row0 + wm + mt * 16 + g;
        int r1 = r0 + 8;
        float sc0 = 1.f, sh0 = 0.f, sc1 = 1.f, sh1 = 0.f;
        if (bg) {
            if (r0 < M) {
                float inv = bg[r0] * rsqrtf(bv[r0] + EPS);
                sc0 = inv; sh0 = bb[r0] - bm[r0] * inv;
            }
            if (r1 < M) {
                float inv = bg[r1] * rsqrtf(bv[r1] + EPS);
                sc1 = inv; sh1 = bb[r1] - bm[r1] * inv;
            }
        }
#pragma unroll
        for (int nt = 0; nt < 4; nt++) {
            int cc = col0 + wn + nt * 8 + 2 * t;
            if (cc < N) {
                if (r0 < M)
                    *(float2*)&Cb[(size_t)r0 * N + cc] =
                        make_float2(c[mt][nt][0] * sc0 + sh0, c[mt][nt][1] * sc0 + sh0);
                if (r1 < M)
                    *(float2*)&Cb[(size_t)r1 * N + cc] =
                        make_float2(c[mt][nt][2] * sc1 + sh1, c[mt][nt][3] * sc1 + sh1);
            }
        }
    }
}

// ---------------------------------------------------------------------------
// fp16 attention with PARALLEL softmax (4 threads/row, all 256 threads).
// Residual staged together with Q. P packed into a separate buffer Psm.
// ---------------------------------------------------------------------------
__global__ void __launch_bounds__(256, 1)
attn_f16_kernel(const float* __restrict__ qb,
                const float* __restrict__ kvb,
                const float* __restrict__ resb,
                const float* __restrict__ lng,
                const float* __restrict__ lnb,
                float* __restrict__ out)
{
    extern __shared__ uint32_t smu[];
    uint32_t* Qsm = smu;                        // [64][QS2]
    uint32_t* Ksm = Qsm + 64 * QS2;             // [32][KS2]
    uint32_t* Vsm = Ksm + 32 * KS2;             // [KPJ][VS2]
    uint32_t* Psm = Vsm + KPJ * VS2;            // [64][PS]
    float*    Ssm = (float*)(Psm + 64 * PS);    // [64][SS]
    float*    Rsm = Ssm + 64 * SS;              // [64][RS]
    float*    rowZ = Rsm + 64 * RS;             // [64]
    float*    accs = rowZ + 64;                 // [8][64]

    const int bh   = blockIdx.x;
    const int b    = bh >> 3, h = bh & 7;
    const int tid  = threadIdx.x;
    const int wid  = tid >> 5;
    const int lane = tid & 31;
    const int g    = lane >> 2;
    const int t    = lane & 3;
    const int wm   = (wid >> 1) * 16;
    const int wnS  = (wid & 1) * 104;
    const int wnO  = (wid & 1) * 32;

    const float* kbase = kvb + ((size_t)b * (2 * INNER) + h * DH) * S2;
    const float* vbase = kbase + (size_t)INNER * S2;
    const float* qbase = qb   + ((size_t)b * INNER + h * DH) * S1;
    const float* rbase = resb + (size_t)b * DH * S1;

    for (int i = tid; i < 32 * NPAD; i += 256) {
        int kp = i / NPAD, j = i - kp * NPAD;
        float a = 0.f, c = 0.f;
        if (j < S2) {
            a = kbase[(size_t)(2 * kp)     * S2 + j];
            c = kbase[(size_t)(2 * kp + 1) * S2 + j];
        }
        Ksm[kp * KS2 + j] = h2_u32(a, c);
    }
    for (int i = tid; i < KPJ * DH; i += 256) {
        int kpj = i % KPJ, d = i / KPJ;
        float a = 0.f, c = 0.f;
        if (2 * kpj < S2) {
            const float* vp = vbase + (size_t)d * S2 + 2 * kpj;
            a = vp[0]; c = vp[1];
        }
        Vsm[kpj * VS2 + d] = h2_u32(a, c);
    }
    for (int i = tid; i < 8 * 64; i += 256) accs[i] = 0.f;

    const float lg0 = lng[h * DH + lane], lg1 = lng[h * DH + lane + 32];
    const float lb0 = lnb[h * DH + lane], lb1 = lnb[h * DH + lane + 32];

    const int rrow = tid >> 2;   // softmax: row per 4-thread group
    const int part = tid & 3;

    for (int s0 = 0; s0 < S1; s0 += 64) {
        const int len = min(64, S1 - s0);
        __syncthreads();   // prior tile fully consumed (Qsm/Ssm/Psm/Rsm)

        // stage Q (u32) + residual (fp32) — independent buffers
        for (int i = tid; i < 64 * 32; i += 256) {
            int r = i & 63, kp = i >> 6;
            float a = 0.f, c = 0.f;
            if (r < len) {
                const float* qp = qbase + (size_t)(2 * kp) * S1 + s0 + r;
                a = qp[0]; c = qp[S1];
            }
            Qsm[r * QS2 + kp] = h2_u32(a, c);
        }
        for (int i = tid; i < 64 * 64; i += 256) {
            int d = i >> 6, r = i & 63;
            if (r < len) Rsm[r * RS + d] = rbase[(size_t)d * S1 + s0 + r];
        }
        __syncthreads();

        // ---- QK^T
        {
            float c[13][4];
#pragma unroll
            for (int nt = 0; nt < 13; nt++)
#pragma unroll
                for (int l = 0; l < 4; l++) c[nt][l] = 0.f;
#pragma unroll
            for (int ks = 0; ks < 4; ks++) {
                unsigned int af[4], bf[13][2];
                af[0] = Qsm[(wm + g    ) * QS2 + ks * 8 + t];
                af[1] = Qsm[(wm + g + 8) * QS2 + ks * 8 + t];
                af[2] = Qsm[(wm + g    ) * QS2 + ks * 8 + t + 4];
                af[3] = Qsm[(wm + g + 8) * QS2 + ks * 8 + t + 4];
#pragma unroll
                for (int nt = 0; nt < 13; nt++) {
                    int nb = wnS + nt * 8 + g;
                    bf[nt][0] = Ksm[(ks * 8 + t    ) * KS2 + nb];
                    bf[nt][1] = Ksm[(ks * 8 + t + 4) * KS2 + nb];
                }
#pragma unroll
                for (int nt = 0; nt < 13; nt++)
                    mma_f16(c[nt], af, bf[nt]);
            }
#pragma unroll
            for (int nt = 0; nt < 13; nt++) {
                int col = wnS + nt * 8 + 2 * t;
                *(float2*)&Ssm[(wm + g    ) * SS + col] =
                    make_float2(c[nt][0] * ATT_SCALE, c[nt][1] * ATT_SCALE);
                *(float2*)&Ssm[(wm + g + 8) * SS + col] =
                    make_float2(c[nt][2] * ATT_SCALE, c[nt][3] * ATT_SCALE);
            }
        }
        __syncthreads();

        // ---- parallel softmax: 4 threads per row
        {
            const float* Srow = &Ssm[rrow * SS];
            uint32_t* Prow = &Psm[rrow * PS];

            float mx = -1e30f;
            for (int j = part; j < S2; j += 4) mx = fmaxf(mx, Srow[j]);
            mx = fmaxf(mx, __shfl_xor_sync(0xffffffffu, mx, 1));
            mx = fmaxf(mx, __shfl_xor_sync(0xffffffffu, mx, 2));

            float z = 0.f;
            for (int kp = part; kp < 98; kp += 4) {
                float e0 = __expf(Srow[2 * kp]     - mx);
                float e1 = __expf(Srow[2 * kp + 1] - mx);
                z += e0 + e1;
                Prow[kp] = h2_u32(e0, e1);
            }
            z += __shfl_xor_sync(0xffffffffu, z, 1);
            z += __shfl_xor_sync(0xffffffffu, z, 2);
            if (part == 0) rowZ[rrow] = z;
            for (int kp = 98 + part; kp < KPJ; kp += 4) Prow[kp] = 0u;
        }
        __syncthreads();

        // ---- PV
        {
            float o[4][4];
#pragma unroll
            for (int nt = 0; nt < 4; nt++)
#pragma unroll
                for (int l = 0; l < 4; l++) o[nt][l] = 0.f;

#pragma unroll
            for (int ks = 0; ks < 13; ks++) {
                unsigned int af[4], bf[4][2];
                af[0] = Psm[(wm + g    ) * PS + ks * 8 + t];
                af[1] = Psm[(wm + g + 8) * PS + ks * 8 + t];
                af[2] = Psm[(wm + g    ) * PS + ks * 8 + t + 4];
                af[3] = Psm[(wm + g + 8) * PS + ks * 8 + t + 4];
#pragma unroll
                for (int nt = 0; nt < 4; nt++) {
                    int nb = wnO + nt * 8 + g;
                    bf[nt][0] = Vsm[(ks * 8 + t    ) * VS2 + nb];
                    bf[nt][1] = Vsm[(ks * 8 + t + 4) * VS2 + nb];
                }
#pragma unroll
                for (int nt = 0; nt < 4; nt++)
                    mma_f16(o[nt], af, bf[nt]);
            }
            int r0 = wm + g, r1 = wm + g + 8;
            float rz0 = 1.f / rowZ[r0], rz1 = 1.f / rowZ[r1];
#pragma unroll
            for (int nt = 0; nt < 4; nt++) {
                int d0 = wnO + nt * 8 + 2 * t;
                Rsm[r0 * RS + d0]     += o[nt][0] * rz0;
                Rsm[r0 * RS + d0 + 1] += o[nt][1] * rz0;
                Rsm[r1 * RS + d0]     += o[nt][2] * rz1;
                Rsm[r1 * RS + d0 + 1] += o[nt][3] * rz1;
            }
        }
        __syncthreads();

        // ---- LayerNorm + spatial-mean accumulation
        for (int r = wid; r < len; r += 8) {
            float x0 = Rsm[r * RS + lane], x1 = Rsm[r * RS + lane + 32];
            float sum = x0 + x1, sq = x0 * x0 + x1 * x1;
#pragma unroll
            for (int o2 = 16; o2 > 0; o2 >>= 1) {
                sum += __shfl_xor_sync(0xffffffffu, sum, o2);
                sq  += __shfl_xor_sync(0xffffffffu, sq, o2);
            }
            float mean = sum * (1.f / 64.f);
            float var  = fmaxf(sq * (1.f / 64.f) - mean * mean, 0.f);
            float rs   = 1.f / (sqrtf(var) + EPS);
            accs[wid * 64 + lane]      += (x0 - mean) * rs * lg0 + lb0;
            accs[wid * 64 + lane + 32] += (x1 - mean) * rs * lg1 + lb1;
        }
    }
    __syncthreads();
    if (tid < 64) {
        float s = 0.f;
#pragma unroll
        for (int w2 = 0; w2 < 8; w2++) s += accs[w2 * 64 + tid];
        out[((size_t)b * HEADS + h) * DH + tid] = s * (1.f / 784.f);
    }
}

// ---------------------------------------------------------------------------
extern "C" void kernel_launch(void* const* d_in, const int* in_sizes, int n_in,
                              void* d_out, int out_size)
{
    const float* x      = (const float*)d_in[0];
    const float* w_dwq  = (const float*)d_in[1];
    const float* w_pwq  = (const float*)d_in[2];
    const float* w_dwkv = (const float*)d_in[3];
    const float* w_pwkv = (const float*)d_in[4];
    const float* w_ds   = (const float*)d_in[5];
    const float* ln_g   = (const float*)d_in[6];
    const float* ln_b   = (const float*)d_in[7];
    const float* bnq_g  = (const float*)d_in[8];
    const float* bnq_b  = (const float*)d_in[9];
    const float* bnq_m  = (const float*)d_in[10];
    const float* bnq_v  = (const float*)d_in[11];
    const float* bnkv_g = (const float*)d_in[12];
    const float* bnkv_b = (const float*)d_in[13];
    const float* bnkv_m = (const float*)d_in[14];
    const float* bnkv_v = (const float*)d_in[15];
    const float* bnds_g = (const float*)d_in[16];
    const float* bnds_b = (const float*)d_in[17];
    const float* bnds_m = (const float*)d_in[18];
    const float* bnds_v = (const float*)d_in[19];
    float* out = (float*)d_out;

    void *p_dqh, *p_dkvh, *p_xh, *p_wqh, *p_wkvh, *p_wdsh, *p_q, *p_kv, *p_res;
    cudaGetSymbolAddress(&p_dqh,  g_dqh);
    cudaGetSymbolAddress(&p_dkvh, g_dkvh);
    cudaGetSymbolAddress(&p_xh,   g_xh);
    cudaGetSymbolAddress(&p_wqh,  g_wqh);
    cudaGetSymbolAddress(&p_wkvh, g_wkvh);
    cudaGetSymbolAddress(&p_wdsh, g_wdsh);
    cudaGetSymbolAddress(&p_q,    g_q);
    cudaGetSymbolAddress(&p_kv,   g_kv);
    cudaGetSymbolAddress(&p_res,  g_res);

    const size_t gemm_smem = (size_t)STAGES * (ASTG + BSTG) * sizeof(uint32_t);
    cudaFuncSetAttribute(gemm_f16_kernel,
                         cudaFuncAttributeMaxDynamicSharedMemorySize, (int)gemm_smem);

    { int n = INNER * KU; pack_w_kernel<<<(n + 255) / 256, 256>>>(w_pwq, (uint32_t*)p_wqh, n); }
    dwconv_smem_kernel<<<NB * KU, 256>>>(
        x, w_dwq, bnq_g, bnq_b, bnq_m, bnq_v, (uint32_t*)p_dqh, 1, HH, WW);
    { int n = 2 * INNER * KU; pack_w_kernel<<<(n + 255) / 256, 256>>>(w_pwkv, (uint32_t*)p_wkvh, n); }
    {
        dim3 grid((S1 + 127) / 128, INNER / 128, NB);
        gemm_f16_kernel<<<grid, 256, gemm_smem>>>(
            (const uint32_t*)p_wqh, (const uint32_t*)p_dqh, (float*)p_q,
            INNER, S1, nullptr, nullptr, nullptr, nullptr);
    }
    dwconv_smem_kernel<<<NB * KU, 256>>>(
        x, w_dwkv, bnkv_g, bnkv_b, bnkv_m, bnkv_v, (uint32_t*)p_dkvh, 2, 14, 14);
    { int n = DH * KU; pack_w_kernel<<<(n + 255) / 256, 256>>>(w_ds, (uint32_t*)p_wdsh, n); }
    { int t2 = NB * KU * (S1 / 2); pack_x_kernel<<<(t2 + 255) / 256, 256>>>(x, (uint32_t*)p_xh, t2); }
    {
        dim3 grid((S2 + 127) / 128, (2 * INNER) / 128, NB);
        gemm_f16_kernel<<<grid, 256, gemm_smem>>>(
            (const uint32_t*)p_wkvh, (const uint32_t*)p_dkvh, (float*)p_kv,
            2 * INNER, S2, nullptr, nullptr, nullptr, nullptr);
    }
    {
        dim3 grid((S1 + 127) / 128, 1, NB);
        gemm_f16_kernel<<<grid, 256, gemm_smem>>>(
            (const uint32_t*)p_wdsh, (const uint32_t*)p_xh, (float*)p_res,
            DH, S1, bnds_g, bnds_b, bnds_m, bnds_v);
    }
    {
        size_t smem = (size_t)(64 * QS2 + 32 * KS2 + KPJ * VS2 + 64 * PS +
                               64 * SS + 64 * RS + 64 + 8 * 64) * 4;
        cudaFuncSetAttribute(attn_f16_kernel,
                             cudaFuncAttributeMaxDynamicSharedMemorySize, (int)smem);
        attn_f16_kernel<<<NB * HEADS, 256, smem>>>(
            (const float*)p_q, (const float*)p_kv, (const float*)p_res,
            ln_g, ln_b, out);
    }
}

// round 12
// speedup vs baseline: 1.4189x; 1.2902x over previous
#include <cuda_runtime.h>
#include <cuda_fp16.h>
#include <math.h>
#include <stdint.h>

#define NB 64
#define CH 640
#define HH 28
#define WW 28
#define S1 784
#define S2 196
#define HEADS 8
#define DH 64
#define INNER 512
#define EPS 1e-5f
#define ATT_SCALE 0.125f
#define KU (CH / 2)
#define PW 30

// fp16 attention tiling
#define NPAD 208
#define QS2  36
#define KS2  232
#define VS2  72
#define PS   108   // P/score (half2) row stride: rrow*12+part covers all banks
#define RS   68
#define KPJ  104

// ---- static scratch ----
__device__ uint32_t g_dqh [NB * KU * S1];
__device__ uint32_t g_dkvh[NB * KU * S2];
__device__ uint32_t g_xh  [NB * KU * S1];
__device__ uint32_t g_wqh [INNER * KU];
__device__ uint32_t g_wkvh[2 * INNER * KU];
__device__ uint32_t g_wdsh[DH * KU];
__device__ float g_q  [NB * INNER * S1];
__device__ float g_kv [NB * 2 * INNER * S2];
__device__ float g_res[NB * DH * S1];

// ---------------------------------------------------------------------------
__device__ __forceinline__ uint32_t h2_u32(float a, float b) {
    __half2 h = __floats2half2_rn(a, b);
    return *reinterpret_cast<uint32_t*>(&h);
}

__global__ void pack_w_kernel(const float* __restrict__ in,
                              uint32_t* __restrict__ out, int n)
{
    int i = blockIdx.x * blockDim.x + threadIdx.x;
    if (i >= n) return;
    float2 v = ((const float2*)in)[i];
    out[i] = h2_u32(v.x, v.y);
}

__global__ void pack_x_kernel(const float* __restrict__ x,
                              uint32_t* __restrict__ out, int total2)
{
    int i = blockIdx.x * blockDim.x + threadIdx.x;
    if (i >= total2) return;
    int s2 = i % (S1 / 2);
    int t  = i / (S1 / 2);
    int cp = t % KU;
    int b  = t / KU;
    int s  = 2 * s2;
    const float* xp = x + ((size_t)b * CH + 2 * cp) * S1 + s;
    float2 a = *(const float2*)xp;
    float2 c = *(const float2*)(xp + S1);
    uint2 r;
    r.x = h2_u32(a.x, c.x);
    r.y = h2_u32(a.y, c.y);
    *(uint2*)&out[((size_t)b * KU + cp) * S1 + s] = r;
}

// ---------------------------------------------------------------------------
// Depthwise 3x3 conv + BN, smem-staged (validated R10)
// ---------------------------------------------------------------------------
__global__ void __launch_bounds__(256)
dwconv_smem_kernel(const float* __restrict__ x,
                   const float* __restrict__ w,
                   const float* __restrict__ bg,
                   const float* __restrict__ bb,
                   const float* __restrict__ bm,
                   const float* __restrict__ bv,
                   uint32_t* __restrict__ out,
                   int stride, int Ho, int Wo)
{
    __shared__ float xs0[PW * PW];
    __shared__ float xs1[PW * PW];

    const int blk = blockIdx.x;
    const int cp  = blk % KU;
    const int b   = blk / KU;
    const int c0  = 2 * cp;
    const int tid = threadIdx.x;

    const float* xp0 = x + ((size_t)b * CH + c0) * S1;
    const float* xp1 = xp0 + S1;

    for (int i = tid; i < PW * PW; i += 256) { xs0[i] = 0.f; xs1[i] = 0.f; }
    __syncthreads();
    for (int i = tid; i < S1; i += 256) {
        int yy = i / WW, xx = i - yy * WW;
        int d = (yy + 1) * PW + xx + 1;
        xs0[d] = xp0[i];
        xs1[d] = xp1[i];
    }

    float w0[9], w1[9];
#pragma unroll
    for (int k = 0; k < 9; k++) {
        w0[k] = w[c0 * 9 + k];
        w1[k] = w[c0 * 9 + 9 + k];
    }
    const float i0 = bg[c0] * rsqrtf(bv[c0] + EPS);
    const float i1 = bg[c0 + 1] * rsqrtf(bv[c0 + 1] + EPS);
    const float s0 = bb[c0] - bm[c0] * i0;
    const float s1 = bb[c0 + 1] - bm[c0 + 1] * i1;
    __syncthreads();

    const int total = Ho * Wo;
    uint32_t* op = out + (size_t)((size_t)b * KU + cp) * total;
    for (int o = tid; o < total; o += 256) {
        int yo = o / Wo, xo = o - yo * Wo;
        int base = (yo * stride) * PW + xo * stride;
        float a0 = 0.f, a1 = 0.f;
#pragma unroll
        for (int dy = 0; dy < 3; dy++)
#pragma unroll
            for (int dx = 0; dx < 3; dx++) {
                int off = base + dy * PW + dx;
                a0 += xs0[off] * w0[dy * 3 + dx];
                a1 += xs1[off] * w1[dy * 3 + dx];
            }
        op[o] = h2_u32(a0 * i0 + s0, a1 * i1 + s1);
    }
}

// ---------------------------------------------------------------------------
__device__ __forceinline__ void mma_f16(float* c, const unsigned int* a,
                                        const unsigned int* b)
{
    asm volatile(
        "mma.sync.aligned.m16n8k16.row.col.f32.f16.f16.f32 "
        "{%0,%1,%2,%3}, {%4,%5,%6,%7}, {%8,%9}, {%0,%1,%2,%3};\n"
        : "+f"(c[0]), "+f"(c[1]), "+f"(c[2]), "+f"(c[3])
        : "r"(a[0]), "r"(a[1]), "r"(a[2]), "r"(a[3]), "r"(b[0]), "r"(b[1]));
}

__device__ __forceinline__ void cp_async16(uint32_t* smem_dst, const uint32_t* gsrc,
                                           bool valid)
{
    unsigned int saddr = (unsigned int)__cvta_generic_to_shared(smem_dst);
    int sz = valid ? 16 : 0;
    asm volatile("cp.async.ca.shared.global [%0], [%1], 16, %2;\n"
                 :: "r"(saddr), "l"(gsrc), "r"(sz));
}
#define CP_COMMIT() asm volatile("cp.async.commit_group;\n" ::: "memory")
#define CP_WAIT2()  asm volatile("cp.async.wait_group 2;\n" ::: "memory")

// ---------------------------------------------------------------------------
// fp16 cp.async 4-stage pipelined GEMM (validated R8, unchanged)
// ---------------------------------------------------------------------------
#define PA 20
#define PB 136
#define STAGES 4
#define ASTG (128 * PA)
#define BSTG (16 * PB)

__global__ void __launch_bounds__(256, 2)
gemm_f16_kernel(const uint32_t* __restrict__ A,
                const uint32_t* __restrict__ Bmat,
                float* __restrict__ C,
                int M, int N,
                const float* __restrict__ bg,
                const float* __restrict__ bb,
                const float* __restrict__ bm,
                const float* __restrict__ bv)
{
    extern __shared__ __align__(16) uint32_t smem[];
    uint32_t* As = smem;
    uint32_t* Bs = smem + STAGES * ASTG;

    const int tid  = threadIdx.x;
    const int lane = tid & 31;
    const int wid  = tid >> 5;
    const int wm   = (wid >> 2) * 64;
    const int wn   = (wid & 3) * 32;
    const int g    = lane >> 2;
    const int t    = lane & 3;

    const int row0  = blockIdx.y * 128;
    const int col0  = blockIdx.x * 128;
    const int batch = blockIdx.z;
    const uint32_t* Bb = Bmat + (size_t)batch * KU * N;
    float*          Cb = C    + (size_t)batch * M * N;

    const int ar  = tid >> 1;
    const int ac  = (tid & 1) * 8;
    const int br  = tid >> 4;
    const int bc  = (tid & 15) * 8;
    const bool aok = (row0 + ar) < M;
    const bool bok = (col0 + bc) < N;

    const uint32_t* ap = A  + (size_t)(aok ? (row0 + ar) : 0) * KU + ac;
    const uint32_t* bp = Bb + (size_t)br * N + (bok ? (col0 + bc) : 0);

    float c[4][4][4];
#pragma unroll
    for (int i = 0; i < 4; i++)
#pragma unroll
        for (int j = 0; j < 4; j++)
#pragma unroll
            for (int l = 0; l < 4; l++) c[i][j][l] = 0.f;

    const int NKT = KU / 16;

#define ISSUE(kt_)                                                              \
    do {                                                                        \
        int s_ = (kt_) & (STAGES - 1);                                          \
        int k0_ = (kt_) * 16;                                                   \
        cp_async16(&As[s_ * ASTG + ar * PA + ac],     ap + k0_,     aok);       \
        cp_async16(&As[s_ * ASTG + ar * PA + ac + 4], ap + k0_ + 4, aok);       \
        cp_async16(&Bs[s_ * BSTG + br * PB + bc],     bp + (size_t)k0_ * N,     bok); \
        cp_async16(&Bs[s_ * BSTG + br * PB + bc + 4], bp + (size_t)k0_ * N + 4, bok); \
    } while (0)

#pragma unroll
    for (int kt = 0; kt < STAGES - 1; kt++) { ISSUE(kt); CP_COMMIT(); }

    for (int kt = 0; kt < NKT; kt++) {
        CP_WAIT2();
        __syncthreads();

        const uint32_t* Asu = &As[(kt & (STAGES - 1)) * ASTG];
        const uint32_t* Bsu = &Bs[(kt & (STAGES - 1)) * BSTG];
#pragma unroll
        for (int ks = 0; ks < 2; ks++) {
            unsigned int af[4][4], bf[4][2];
#pragma unroll
            for (int mt = 0; mt < 4; mt++) {
                int mb = wm + mt * 16;
                af[mt][0] = Asu[(mb + g    ) * PA + ks * 8 + t];
                af[mt][1] = Asu[(mb + g + 8) * PA + ks * 8 + t];
                af[mt][2] = Asu[(mb + g    ) * PA + ks * 8 + t + 4];
                af[mt][3] = Asu[(mb + g + 8) * PA + ks * 8 + t + 4];
            }
#pragma unroll
            for (int nt = 0; nt < 4; nt++) {
                int nb = wn + nt * 8 + g;
                bf[nt][0] = Bsu[(ks * 8 + t    ) * PB + nb];
                bf[nt][1] = Bsu[(ks * 8 + t + 4) * PB + nb];
            }
#pragma unroll
            for (int mt = 0; mt < 4; mt++)
#pragma unroll
                for (int nt = 0; nt < 4; nt++)
                    mma_f16(c[mt][nt], af[mt], bf[nt]);
        }

        if (kt + STAGES - 1 < NKT) ISSUE(kt + STAGES - 1);
        CP_COMMIT();
    }
#undef ISSUE

#pragma unroll
    for (int mt = 0; mt < 4; mt++) {
        int r0 = row0 + wm + mt * 16 + g;
        int r1 = r0 + 8;
        float sc0 = 1.f, sh0 = 0.f, sc1 = 1.f, sh1 = 0.f;
        if (bg) {
            if (r0 < M) {
                float inv = bg[r0] * rsqrtf(bv[r0] + EPS);
                sc0 = inv; sh0 = bb[r0] - bm[r0] * inv;
            }
            if (r1 < M) {
                float inv = bg[r1] * rsqrtf(bv[r1] + EPS);
                sc1 = inv; sh1 = bb[r1] - bm[r1] * inv;
            }
        }
#pragma unroll
        for (int nt = 0; nt < 4; nt++) {
            int cc = col0 + wn + nt * 8 + 2 * t;
            if (cc < N) {
                if (r0 < M)
                    *(float2*)&Cb[(size_t)r0 * N + cc] =
                        make_float2(c[mt][nt][0] * sc0 + sh0, c[mt][nt][1] * sc0 + sh0);
                if (r1 < M)
                    *(float2*)&Cb[(size_t)r1 * N + cc] =
                        make_float2(c[mt][nt][2] * sc1 + sh1, c[mt][nt][3] * sc1 + sh1);
            }
        }
    }
}

// ---------------------------------------------------------------------------
// fp16 attention v3: scores packed half2 straight from QK (no fp32 S buffer),
// in-place softmax (4 threads/row), register LN accumulators, 2 CTAs/SM.
// ---------------------------------------------------------------------------
__global__ void __launch_bounds__(256, 2)
attn_f16_kernel(const float* __restrict__ qb,
                const float* __restrict__ kvb,
                const float* __restrict__ resb,
                const float* __restrict__ lng,
                const float* __restrict__ lnb,
                float* __restrict__ out)
{
    extern __shared__ uint32_t smu[];
    uint32_t* Qsm = smu;                        // [64][QS2]
    uint32_t* Ksm = Qsm + 64 * QS2;             // [32][KS2]
    uint32_t* Vsm = Ksm + 32 * KS2;             // [KPJ][VS2]
    uint32_t* Psm = Vsm + KPJ * VS2;            // [64][PS] scores->P (half2)
    float*    Rsm = (float*)(Psm + 64 * PS);    // [64][RS]
    float*    rowZ = Rsm + 64 * RS;             // [64]

    const int bh   = blockIdx.x;
    const int b    = bh >> 3, h = bh & 7;
    const int tid  = threadIdx.x;
    const int wid  = tid >> 5;
    const int lane = tid & 31;
    const int g    = lane >> 2;
    const int t    = lane & 3;
    const int wm   = (wid >> 1) * 16;
    const int wnS  = (wid & 1) * 104;   // score columns (element units)
    const int wnO  = (wid & 1) * 32;

    const float* kbase = kvb + ((size_t)b * (2 * INNER) + h * DH) * S2;
    const float* vbase = kbase + (size_t)INNER * S2;
    const float* qbase = qb   + ((size_t)b * INNER + h * DH) * S1;
    const float* rbase = resb + (size_t)b * DH * S1;

    for (int i = tid; i < 32 * NPAD; i += 256) {
        int kp = i / NPAD, j = i - kp * NPAD;
        float a = 0.f, c = 0.f;
        if (j < S2) {
            a = kbase[(size_t)(2 * kp)     * S2 + j];
            c = kbase[(size_t)(2 * kp + 1) * S2 + j];
        }
        Ksm[kp * KS2 + j] = h2_u32(a, c);
    }
    for (int i = tid; i < KPJ * DH; i += 256) {
        int kpj = i % KPJ, d = i / KPJ;
        float a = 0.f, c = 0.f;
        if (2 * kpj < S2) {
            const float* vp = vbase + (size_t)d * S2 + 2 * kpj;
            a = vp[0]; c = vp[1];
        }
        Vsm[kpj * VS2 + d] = h2_u32(a, c);
    }

    const float lg0 = lng[h * DH + lane], lg1 = lng[h * DH + lane + 32];
    const float lb0 = lnb[h * DH + lane], lb1 = lnb[h * DH + lane + 32];
    float acc0 = 0.f, acc1 = 0.f;   // per-warp LN accumulators (registers)

    const int rrow = tid >> 2;
    const int part = tid & 3;

    for (int s0 = 0; s0 < S1; s0 += 64) {
        const int len = min(64, S1 - s0);
        __syncthreads();

        // stage Q + residual
        for (int i = tid; i < 64 * 32; i += 256) {
            int r = i & 63, kp = i >> 6;
            float a = 0.f, c = 0.f;
            if (r < len) {
                const float* qp = qbase + (size_t)(2 * kp) * S1 + s0 + r;
                a = qp[0]; c = qp[S1];
            }
            Qsm[r * QS2 + kp] = h2_u32(a, c);
        }
        for (int i = tid; i < 64 * 64; i += 256) {
            int d = i >> 6, r = i & 63;
            if (r < len) Rsm[r * RS + d] = rbase[(size_t)d * S1 + s0 + r];
        }
        __syncthreads();

        // ---- QK^T -> scaled scores packed half2 into Psm
        {
            float c[13][4];
#pragma unroll
            for (int nt = 0; nt < 13; nt++)
#pragma unroll
                for (int l = 0; l < 4; l++) c[nt][l] = 0.f;
#pragma unroll
            for (int ks = 0; ks < 4; ks++) {
                unsigned int af[4], bf[13][2];
                af[0] = Qsm[(wm + g    ) * QS2 + ks * 8 + t];
                af[1] = Qsm[(wm + g + 8) * QS2 + ks * 8 + t];
                af[2] = Qsm[(wm + g    ) * QS2 + ks * 8 + t + 4];
                af[3] = Qsm[(wm + g + 8) * QS2 + ks * 8 + t + 4];
#pragma unroll
                for (int nt = 0; nt < 13; nt++) {
                    int nb = wnS + nt * 8 + g;
                    bf[nt][0] = Ksm[(ks * 8 + t    ) * KS2 + nb];
                    bf[nt][1] = Ksm[(ks * 8 + t + 4) * KS2 + nb];
                }
#pragma unroll
                for (int nt = 0; nt < 13; nt++)
                    mma_f16(c[nt], af, bf[nt]);
            }
            int wp = wnS / 2;   // word offset
#pragma unroll
            for (int nt = 0; nt < 13; nt++) {
                int wcol = wp + nt * 4 + t;
                Psm[(wm + g    ) * PS + wcol] =
                    h2_u32(c[nt][0] * ATT_SCALE, c[nt][1] * ATT_SCALE);
                Psm[(wm + g + 8) * PS + wcol] =
                    h2_u32(c[nt][2] * ATT_SCALE, c[nt][3] * ATT_SCALE);
            }
        }
        __syncthreads();

        // ---- in-place softmax: 4 threads per row (warp-convergent safe)
        {
            uint32_t* Prow = &Psm[rrow * PS];
            float mx = -1e30f;
            for (int kp = part; kp < 98; kp += 4) {
                __half2 hv = *reinterpret_cast<__half2*>(&Prow[kp]);
                float2 f = __half22float2(hv);
                mx = fmaxf(mx, fmaxf(f.x, f.y));
            }
            mx = fmaxf(mx, __shfl_xor_sync(0xffffffffu, mx, 1));
            mx = fmaxf(mx, __shfl_xor_sync(0xffffffffu, mx, 2));

            float z = 0.f;
            for (int kp = part; kp < 98; kp += 4) {
                __half2 hv = *reinterpret_cast<__half2*>(&Prow[kp]);
                float2 f = __half22float2(hv);
                float e0 = __expf(f.x - mx);
                float e1 = __expf(f.y - mx);
                z += e0 + e1;
                Prow[kp] = h2_u32(e0, e1);
            }
            z += __shfl_xor_sync(0xffffffffu, z, 1);
            z += __shfl_xor_sync(0xffffffffu, z, 2);
            if (part == 0) rowZ[rrow] = z;
            for (int kp = 98 + part; kp < KPJ; kp += 4) Prow[kp] = 0u;
        }
        __syncthreads();

        // ---- PV
        {
            float o[4][4];
#pragma unroll
            for (int nt = 0; nt < 4; nt++)
#pragma unroll
                for (int l = 0; l < 4; l++) o[nt][l] = 0.f;

#pragma unroll
            for (int ks = 0; ks < 13; ks++) {
                unsigned int af[4], bf[4][2];
                af[0] = Psm[(wm + g    ) * PS + ks * 8 + t];
                af[1] = Psm[(wm + g + 8) * PS + ks * 8 + t];
                af[2] = Psm[(wm + g    ) * PS + ks * 8 + t + 4];
                af[3] = Psm[(wm + g + 8) * PS + ks * 8 + t + 4];
#pragma unroll
                for (int nt = 0; nt < 4; nt++) {
                    int nb = wnO + nt * 8 + g;
                    bf[nt][0] = Vsm[(ks * 8 + t    ) * VS2 + nb];
                    bf[nt][1] = Vsm[(ks * 8 + t + 4) * VS2 + nb];
                }
#pragma unroll
                for (int nt = 0; nt < 4; nt++)
                    mma_f16(o[nt], af, bf[nt]);
            }
            int r0 = wm + g, r1 = wm + g + 8;
            float rz0 = 1.f / rowZ[r0], rz1 = 1.f / rowZ[r1];
#pragma unroll
            for (int nt = 0; nt < 4; nt++) {
                int d0 = wnO + nt * 8 + 2 * t;
                Rsm[r0 * RS + d0]     += o[nt][0] * rz0;
                Rsm[r0 * RS + d0 + 1] += o[nt][1] * rz0;
                Rsm[r1 * RS + d0]     += o[nt][2] * rz1;
                Rsm[r1 * RS + d0 + 1] += o[nt][3] * rz1;
            }
        }
        __syncthreads();

        // ---- LayerNorm + spatial-mean accumulation (register acc)
        for (int r = wid; r < len; r += 8) {
            float x0 = Rsm[r * RS + lane], x1 = Rsm[r * RS + lane + 32];
            float sum = x0 + x1, sq = x0 * x0 + x1 * x1;
#pragma unroll
            for (int o2 = 16; o2 > 0; o2 >>= 1) {
                sum += __shfl_xor_sync(0xffffffffu, sum, o2);
                sq  += __shfl_xor_sync(0xffffffffu, sq, o2);
            }
            float mean = sum * (1.f / 64.f);
            float var  = fmaxf(sq * (1.f / 64.f) - mean * mean, 0.f);
            float rs   = 1.f / (sqrtf(var) + EPS);
            acc0 += (x0 - mean) * rs * lg0 + lb0;
            acc1 += (x1 - mean) * rs * lg1 + lb1;
        }
    }

    // cross-warp reduction (reuse Psm as fp32 buffer)
    __syncthreads();
    float* red = (float*)Psm;
    red[wid * 64 + lane]      = acc0;
    red[wid * 64 + lane + 32] = acc1;
    __syncthreads();
    if (tid < 64) {
        float s = 0.f;
#pragma unroll
        for (int w2 = 0; w2 < 8; w2++) s += red[w2 * 64 + tid];
        out[((size_t)b * HEADS + h) * DH + tid] = s * (1.f / 784.f);
    }
}

// ---------------------------------------------------------------------------
extern "C" void kernel_launch(void* const* d_in, const int* in_sizes, int n_in,
                              void* d_out, int out_size)
{
    const float* x      = (const float*)d_in[0];
    const float* w_dwq  = (const float*)d_in[1];
    const float* w_pwq  = (const float*)d_in[2];
    const float* w_dwkv = (const float*)d_in[3];
    const float* w_pwkv = (const float*)d_in[4];
    const float* w_ds   = (const float*)d_in[5];
    const float* ln_g   = (const float*)d_in[6];
    const float* ln_b   = (const float*)d_in[7];
    const float* bnq_g  = (const float*)d_in[8];
    const float* bnq_b  = (const float*)d_in[9];
    const float* bnq_m  = (const float*)d_in[10];
    const float* bnq_v  = (const float*)d_in[11];
    const float* bnkv_g = (const float*)d_in[12];
    const float* bnkv_b = (const float*)d_in[13];
    const float* bnkv_m = (const float*)d_in[14];
    const float* bnkv_v = (const float*)d_in[15];
    const float* bnds_g = (const float*)d_in[16];
    const float* bnds_b = (const float*)d_in[17];
    const float* bnds_m = (const float*)d_in[18];
    const float* bnds_v = (const float*)d_in[19];
    float* out = (float*)d_out;

    void *p_dqh, *p_dkvh, *p_xh, *p_wqh, *p_wkvh, *p_wdsh, *p_q, *p_kv, *p_res;
    cudaGetSymbolAddress(&p_dqh,  g_dqh);
    cudaGetSymbolAddress(&p_dkvh, g_dkvh);
    cudaGetSymbolAddress(&p_xh,   g_xh);
    cudaGetSymbolAddress(&p_wqh,  g_wqh);
    cudaGetSymbolAddress(&p_wkvh, g_wkvh);
    cudaGetSymbolAddress(&p_wdsh, g_wdsh);
    cudaGetSymbolAddress(&p_q,    g_q);
    cudaGetSymbolAddress(&p_kv,   g_kv);
    cudaGetSymbolAddress(&p_res,  g_res);

    const size_t gemm_smem = (size_t)STAGES * (ASTG + BSTG) * sizeof(uint32_t);
    cudaFuncSetAttribute(gemm_f16_kernel,
                         cudaFuncAttributeMaxDynamicSharedMemorySize, (int)gemm_smem);

    { int n = INNER * KU; pack_w_kernel<<<(n + 255) / 256, 256>>>(w_pwq, (uint32_t*)p_wqh, n); }
    dwconv_smem_kernel<<<NB * KU, 256>>>(
        x, w_dwq, bnq_g, bnq_b, bnq_m, bnq_v, (uint32_t*)p_dqh, 1, HH, WW);
    { int n = 2 * INNER * KU; pack_w_kernel<<<(n + 255) / 256, 256>>>(w_pwkv, (uint32_t*)p_wkvh, n); }
    {
        dim3 grid((S1 + 127) / 128, INNER / 128, NB);
        gemm_f16_kernel<<<grid, 256, gemm_smem>>>(
            (const uint32_t*)p_wqh, (const uint32_t*)p_dqh, (float*)p_q,
            INNER, S1, nullptr, nullptr, nullptr, nullptr);
    }
    dwconv_smem_kernel<<<NB * KU, 256>>>(
        x, w_dwkv, bnkv_g, bnkv_b, bnkv_m, bnkv_v, (uint32_t*)p_dkvh, 2, 14, 14);
    { int n = DH * KU; pack_w_kernel<<<(n + 255) / 256, 256>>>(w_ds, (uint32_t*)p_wdsh, n); }
    { int t2 = NB * KU * (S1 / 2); pack_x_kernel<<<(t2 + 255) / 256, 256>>>(x, (uint32_t*)p_xh, t2); }
    {
        dim3 grid((S2 + 127) / 128, (2 * INNER) / 128, NB);
        gemm_f16_kernel<<<grid, 256, gemm_smem>>>(
            (const uint32_t*)p_wkvh, (const uint32_t*)p_dkvh, (float*)p_kv,
            2 * INNER, S2, nullptr, nullptr, nullptr, nullptr);
    }
    {
        dim3 grid((S1 + 127) / 128, 1, NB);
        gemm_f16_kernel<<<grid, 256, gemm_smem>>>(
            (const uint32_t*)p_wdsh, (const uint32_t*)p_xh, (float*)p_res,
            DH, S1, bnds_g, bnds_b, bnds_m, bnds_v);
    }
    {
        size_t smem = (size_t)(64 * QS2 + 32 * KS2 + KPJ * VS2 + 64 * PS +
                               64 * RS + 64) * 4;
        cudaFuncSetAttribute(attn_f16_kernel,
                             cudaFuncAttributeMaxDynamicSharedMemorySize, (int)smem);
        attn_f16_kernel<<<NB * HEADS, 256, smem>>>(
            (const float*)p_q, (const float*)p_kv, (const float*)p_res,
            ln_g, ln_b, out);
    }
}

// round 13
// speedup vs baseline: 1.4525x; 1.0236x over previous
#include <cuda_runtime.h>
#include <cuda_fp16.h>
#include <math.h>
#include <stdint.h>

#define NB 64
#define CH 640
#define HH 28
#define WW 28
#define S1 784
#define S2 196
#define HEADS 8
#define DH 64
#define INNER 512
#define EPS 1e-5f
#define ATT_SCALE 0.125f
#define KU (CH / 2)
#define PW 30

// fp16 attention tiling (validated R12)
#define NPAD 208
#define QS2  36
#define KS2  232
#define VS2  72
#define PS   108
#define RS   68
#define KPJ  104

// ---- static scratch ----
__device__ uint32_t g_dqh [NB * KU * S1];
__device__ uint32_t g_dkvh[NB * KU * S2];
__device__ uint32_t g_xh  [NB * KU * S1];
__device__ uint32_t g_wqh [INNER * KU];
__device__ uint32_t g_wkvh[2 * INNER * KU];
__device__ uint32_t g_wdsh[DH * KU];
__device__ float g_q  [NB * INNER * S1];
__device__ float g_kv [NB * 2 * INNER * S2];
__device__ float g_res[NB * DH * S1];

// ---------------------------------------------------------------------------
__device__ __forceinline__ uint32_t h2_u32(float a, float b) {
    __half2 h = __floats2half2_rn(a, b);
    return *reinterpret_cast<uint32_t*>(&h);
}

// ldmatrix x4: loads a 16x16 fp16 A-tile (4 8x8 matrices) -> mma A-frag order.
// saddr = per-lane shared address (lane&15 selects row, lane>>4 selects col half)
__device__ __forceinline__ void ldsm_x4(uint32_t* r, uint32_t saddr) {
    asm volatile("ldmatrix.sync.aligned.m8n8.x4.shared.b16 {%0,%1,%2,%3}, [%4];"
                 : "=r"(r[0]), "=r"(r[1]), "=r"(r[2]), "=r"(r[3]) : "r"(saddr));
}

__global__ void pack_w_kernel(const float* __restrict__ in,
                              uint32_t* __restrict__ out, int n)
{
    int i = blockIdx.x * blockDim.x + threadIdx.x;
    if (i >= n) return;
    float2 v = ((const float2*)in)[i];
    out[i] = h2_u32(v.x, v.y);
}

__global__ void pack_x_kernel(const float* __restrict__ x,
                              uint32_t* __restrict__ out, int total2)
{
    int i = blockIdx.x * blockDim.x + threadIdx.x;
    if (i >= total2) return;
    int s2 = i % (S1 / 2);
    int t  = i / (S1 / 2);
    int cp = t % KU;
    int b  = t / KU;
    int s  = 2 * s2;
    const float* xp = x + ((size_t)b * CH + 2 * cp) * S1 + s;
    float2 a = *(const float2*)xp;
    float2 c = *(const float2*)(xp + S1);
    uint2 r;
    r.x = h2_u32(a.x, c.x);
    r.y = h2_u32(a.y, c.y);
    *(uint2*)&out[((size_t)b * KU + cp) * S1 + s] = r;
}

// ---------------------------------------------------------------------------
// Depthwise 3x3 conv + BN, smem-staged (validated R10)
// ---------------------------------------------------------------------------
__global__ void __launch_bounds__(256)
dwconv_smem_kernel(const float* __restrict__ x,
                   const float* __restrict__ w,
                   const float* __restrict__ bg,
                   const float* __restrict__ bb,
                   const float* __restrict__ bm,
                   const float* __restrict__ bv,
                   uint32_t* __restrict__ out,
                   int stride, int Ho, int Wo)
{
    __shared__ float xs0[PW * PW];
    __shared__ float xs1[PW * PW];

    const int blk = blockIdx.x;
    const int cp  = blk % KU;
    const int b   = blk / KU;
    const int c0  = 2 * cp;
    const int tid = threadIdx.x;

    const float* xp0 = x + ((size_t)b * CH + c0) * S1;
    const float* xp1 = xp0 + S1;

    for (int i = tid; i < PW * PW; i += 256) { xs0[i] = 0.f; xs1[i] = 0.f; }
    __syncthreads();
    for (int i = tid; i < S1; i += 256) {
        int yy = i / WW, xx = i - yy * WW;
        int d = (yy + 1) * PW + xx + 1;
        xs0[d] = xp0[i];
        xs1[d] = xp1[i];
    }

    float w0[9], w1[9];
#pragma unroll
    for (int k = 0; k < 9; k++) {
        w0[k] = w[c0 * 9 + k];
        w1[k] = w[c0 * 9 + 9 + k];
    }
    const float i0 = bg[c0] * rsqrtf(bv[c0] + EPS);
    const float i1 = bg[c0 + 1] * rsqrtf(bv[c0 + 1] + EPS);
    const float s0 = bb[c0] - bm[c0] * i0;
    const float s1 = bb[c0 + 1] - bm[c0 + 1] * i1;
    __syncthreads();

    const int total = Ho * Wo;
    uint32_t* op = out + (size_t)((size_t)b * KU + cp) * total;
    for (int o = tid; o < total; o += 256) {
        int yo = o / Wo, xo = o - yo * Wo;
        int base = (yo * stride) * PW + xo * stride;
        float a0 = 0.f, a1 = 0.f;
#pragma unroll
        for (int dy = 0; dy < 3; dy++)
#pragma unroll
            for (int dx = 0; dx < 3; dx++) {
                int off = base + dy * PW + dx;
                a0 += xs0[off] * w0[dy * 3 + dx];
                a1 += xs1[off] * w1[dy * 3 + dx];
            }
        op[o] = h2_u32(a0 * i0 + s0, a1 * i1 + s1);
    }
}

// ---------------------------------------------------------------------------
__device__ __forceinline__ void mma_f16(float* c, const unsigned int* a,
                                        const unsigned int* b)
{
    asm volatile(
        "mma.sync.aligned.m16n8k16.row.col.f32.f16.f16.f32 "
        "{%0,%1,%2,%3}, {%4,%5,%6,%7}, {%8,%9}, {%0,%1,%2,%3};\n"
        : "+f"(c[0]), "+f"(c[1]), "+f"(c[2]), "+f"(c[3])
        : "r"(a[0]), "r"(a[1]), "r"(a[2]), "r"(a[3]), "r"(b[0]), "r"(b[1]));
}

__device__ __forceinline__ void cp_async16(uint32_t* smem_dst, const uint32_t* gsrc,
                                           bool valid)
{
    unsigned int saddr = (unsigned int)__cvta_generic_to_shared(smem_dst);
    int sz = valid ? 16 : 0;
    asm volatile("cp.async.ca.shared.global [%0], [%1], 16, %2;\n"
                 :: "r"(saddr), "l"(gsrc), "r"(sz));
}
#define CP_COMMIT() asm volatile("cp.async.commit_group;\n" ::: "memory")
#define CP_WAIT2()  asm volatile("cp.async.wait_group 2;\n" ::: "memory")

// ---------------------------------------------------------------------------
// fp16 cp.async 4-stage pipelined GEMM; A-fragments via ldmatrix.x4
// ---------------------------------------------------------------------------
#define PA 20
#define PB 136
#define STAGES 4
#define ASTG (128 * PA)
#define BSTG (16 * PB)

__global__ void __launch_bounds__(256, 2)
gemm_f16_kernel(const uint32_t* __restrict__ A,
                const uint32_t* __restrict__ Bmat,
                float* __restrict__ C,
                int M, int N,
                const float* __restrict__ bg,
                const float* __restrict__ bb,
                const float* __restrict__ bm,
                const float* __restrict__ bv)
{
    extern __shared__ __align__(16) uint32_t smem[];
    uint32_t* As = smem;
    uint32_t* Bs = smem + STAGES * ASTG;

    const int tid  = threadIdx.x;
    const int lane = tid & 31;
    const int wid  = tid >> 5;
    const int wm   = (wid >> 2) * 64;
    const int wn   = (wid & 3) * 32;
    const int g    = lane >> 2;
    const int t    = lane & 3;
    const int rsel = lane & 15;          // ldmatrix row select
    const int csel = (lane >> 4) * 4;    // ldmatrix col-half select (u32)

    const int row0  = blockIdx.y * 128;
    const int col0  = blockIdx.x * 128;
    const int batch = blockIdx.z;
    const uint32_t* Bb = Bmat + (size_t)batch * KU * N;
    float*          Cb = C    + (size_t)batch * M * N;

    const int ar  = tid >> 1;
    const int ac  = (tid & 1) * 8;
    const int br  = tid >> 4;
    const int bc  = (tid & 15) * 8;
    const bool aok = (row0 + ar) < M;
    const bool bok = (col0 + bc) < N;

    const uint32_t* ap = A  + (size_t)(aok ? (row0 + ar) : 0) * KU + ac;
    const uint32_t* bp = Bb + (size_t)br * N + (bok ? (col0 + bc) : 0);

    const uint32_t as_base = (uint32_t)__cvta_generic_to_shared(As);

    float c[4][4][4];
#pragma unroll
    for (int i = 0; i < 4; i++)
#pragma unroll
        for (int j = 0; j < 4; j++)
#pragma unroll
            for (int l = 0; l < 4; l++) c[i][j][l] = 0.f;

    const int NKT = KU / 16;

#define ISSUE(kt_)                                                              \
    do {                                                                        \
        int s_ = (kt_) & (STAGES - 1);                                          \
        int k0_ = (kt_) * 16;                                                   \
        cp_async16(&As[s_ * ASTG + ar * PA + ac],     ap + k0_,     aok);       \
        cp_async16(&As[s_ * ASTG + ar * PA + ac + 4], ap + k0_ + 4, aok);       \
        cp_async16(&Bs[s_ * BSTG + br * PB + bc],     bp + (size_t)k0_ * N,     bok); \
        cp_async16(&Bs[s_ * BSTG + br * PB + bc + 4], bp + (size_t)k0_ * N + 4, bok); \
    } while (0)

#pragma unroll
    for (int kt = 0; kt < STAGES - 1; kt++) { ISSUE(kt); CP_COMMIT(); }

    for (int kt = 0; kt < NKT; kt++) {
        CP_WAIT2();
        __syncthreads();

        const int cur = kt & (STAGES - 1);
        const uint32_t a_s = as_base + cur * (ASTG * 4);
        const uint32_t* Bsu = &Bs[cur * BSTG];
#pragma unroll
        for (int ks = 0; ks < 2; ks++) {
            unsigned int af[4][4], bf[4][2];
#pragma unroll
            for (int mt = 0; mt < 4; mt++)
                ldsm_x4(af[mt],
                        a_s + 4u * ((wm + mt * 16 + rsel) * PA + ks * 8 + csel));
#pragma unroll
            for (int nt = 0; nt < 4; nt++) {
                int nb = wn + nt * 8 + g;
                bf[nt][0] = Bsu[(ks * 8 + t    ) * PB + nb];
                bf[nt][1] = Bsu[(ks * 8 + t + 4) * PB + nb];
            }
#pragma unroll
            for (int mt = 0; mt < 4; mt++)
#pragma unroll
                for (int nt = 0; nt < 4; nt++)
                    mma_f16(c[mt][nt], af[mt], bf[nt]);
        }

        if (kt + STAGES - 1 < NKT) ISSUE(kt + STAGES - 1);
        CP_COMMIT();
    }
#undef ISSUE

#pragma unroll
    for (int mt = 0; mt < 4; mt++) {
        int r0 = row0 + wm + mt * 16 + g;
        int r1 = r0 + 8;
        float sc0 = 1.f, sh0 = 0.f, sc1 = 1.f, sh1 = 0.f;
        if (bg) {
            if (r0 < M) {
                float inv = bg[r0] * rsqrtf(bv[r0] + EPS);
                sc0 = inv; sh0 = bb[r0] - bm[r0] * inv;
            }
            if (r1 < M) {
                float inv = bg[r1] * rsqrtf(bv[r1] + EPS);
                sc1 = inv; sh1 = bb[r1] - bm[r1] * inv;
            }
        }
#pragma unroll
        for (int nt = 0; nt < 4; nt++) {
            int cc = col0 + wn + nt * 8 + 2 * t;
            if (cc < N) {
                if (r0 < M)
                    *(float2*)&Cb[(size_t)r0 * N + cc] =
                        make_float2(c[mt][nt][0] * sc0 + sh0, c[mt][nt][1] * sc0 + sh0);
                if (r1 < M)
                    *(float2*)&Cb[(size_t)r1 * N + cc] =
                        make_float2(c[mt][nt][2] * sc1 + sh1, c[mt][nt][3] * sc1 + sh1);
            }
        }
    }
}

// ---------------------------------------------------------------------------
// fp16 attention v3 + ldmatrix A-frags (QK from Qsm, PV from Psm)
// ---------------------------------------------------------------------------
__global__ void __launch_bounds__(256, 2)
attn_f16_kernel(const float* __restrict__ qb,
                const float* __restrict__ kvb,
                const float* __restrict__ resb,
                const float* __restrict__ lng,
                const float* __restrict__ lnb,
                float* __restrict__ out)
{
    extern __shared__ uint32_t smu[];
    uint32_t* Qsm = smu;                        // [64][QS2]
    uint32_t* Ksm = Qsm + 64 * QS2;             // [32][KS2]
    uint32_t* Vsm = Ksm + 32 * KS2;             // [KPJ][VS2]
    uint32_t* Psm = Vsm + KPJ * VS2;            // [64][PS]
    float*    Rsm = (float*)(Psm + 64 * PS);    // [64][RS]
    float*    rowZ = Rsm + 64 * RS;             // [64]

    const int bh   = blockIdx.x;
    const int b    = bh >> 3, h = bh & 7;
    const int tid  = threadIdx.x;
    const int wid  = tid >> 5;
    const int lane = tid & 31;
    const int g    = lane >> 2;
    const int t    = lane & 3;
    const int rsel = lane & 15;
    const int csel = (lane >> 4) * 4;
    const int wm   = (wid >> 1) * 16;
    const int wnS  = (wid & 1) * 104;
    const int wnO  = (wid & 1) * 32;

    const uint32_t qs_base = (uint32_t)__cvta_generic_to_shared(Qsm);
    const uint32_t ps_base = (uint32_t)__cvta_generic_to_shared(Psm);

    const float* kbase = kvb + ((size_t)b * (2 * INNER) + h * DH) * S2;
    const float* vbase = kbase + (size_t)INNER * S2;
    const float* qbase = qb   + ((size_t)b * INNER + h * DH) * S1;
    const float* rbase = resb + (size_t)b * DH * S1;

    for (int i = tid; i < 32 * NPAD; i += 256) {
        int kp = i / NPAD, j = i - kp * NPAD;
        float a = 0.f, c = 0.f;
        if (j < S2) {
            a = kbase[(size_t)(2 * kp)     * S2 + j];
            c = kbase[(size_t)(2 * kp + 1) * S2 + j];
        }
        Ksm[kp * KS2 + j] = h2_u32(a, c);
    }
    for (int i = tid; i < KPJ * DH; i += 256) {
        int kpj = i % KPJ, d = i / KPJ;
        float a = 0.f, c = 0.f;
        if (2 * kpj < S2) {
            const float* vp = vbase + (size_t)d * S2 + 2 * kpj;
            a = vp[0]; c = vp[1];
        }
        Vsm[kpj * VS2 + d] = h2_u32(a, c);
    }

    const float lg0 = lng[h * DH + lane], lg1 = lng[h * DH + lane + 32];
    const float lb0 = lnb[h * DH + lane], lb1 = lnb[h * DH + lane + 32];
    float acc0 = 0.f, acc1 = 0.f;

    const int rrow = tid >> 2;
    const int part = tid & 3;

    for (int s0 = 0; s0 < S1; s0 += 64) {
        const int len = min(64, S1 - s0);
        __syncthreads();

        for (int i = tid; i < 64 * 32; i += 256) {
            int r = i & 63, kp = i >> 6;
            float a = 0.f, c = 0.f;
            if (r < len) {
                const float* qp = qbase + (size_t)(2 * kp) * S1 + s0 + r;
                a = qp[0]; c = qp[S1];
            }
            Qsm[r * QS2 + kp] = h2_u32(a, c);
        }
        for (int i = tid; i < 64 * 64; i += 256) {
            int d = i >> 6, r = i & 63;
            if (r < len) Rsm[r * RS + d] = rbase[(size_t)d * S1 + s0 + r];
        }
        __syncthreads();

        // ---- QK^T -> scaled scores packed half2 into Psm
        {
            float c[13][4];
#pragma unroll
            for (int nt = 0; nt < 13; nt++)
#pragma unroll
                for (int l = 0; l < 4; l++) c[nt][l] = 0.f;
#pragma unroll
            for (int ks = 0; ks < 4; ks++) {
                unsigned int af[4], bf[13][2];
                ldsm_x4(af, qs_base + 4u * ((wm + rsel) * QS2 + ks * 8 + csel));
#pragma unroll
                for (int nt = 0; nt < 13; nt++) {
                    int nb = wnS + nt * 8 + g;
                    bf[nt][0] = Ksm[(ks * 8 + t    ) * KS2 + nb];
                    bf[nt][1] = Ksm[(ks * 8 + t + 4) * KS2 + nb];
                }
#pragma unroll
                for (int nt = 0; nt < 13; nt++)
                    mma_f16(c[nt], af, bf[nt]);
            }
            int wp = wnS / 2;
#pragma unroll
            for (int nt = 0; nt < 13; nt++) {
                int wcol = wp + nt * 4 + t;
                Psm[(wm + g    ) * PS + wcol] =
                    h2_u32(c[nt][0] * ATT_SCALE, c[nt][1] * ATT_SCALE);
                Psm[(wm + g + 8) * PS + wcol] =
                    h2_u32(c[nt][2] * ATT_SCALE, c[nt][3] * ATT_SCALE);
            }
        }
        __syncthreads();

        // ---- in-place softmax: 4 threads per row
        {
            uint32_t* Prow = &Psm[rrow * PS];
            float mx = -1e30f;
            for (int kp = part; kp < 98; kp += 4) {
                __half2 hv = *reinterpret_cast<__half2*>(&Prow[kp]);
                float2 f = __half22float2(hv);
                mx = fmaxf(mx, fmaxf(f.x, f.y));
            }
            mx = fmaxf(mx, __shfl_xor_sync(0xffffffffu, mx, 1));
            mx = fmaxf(mx, __shfl_xor_sync(0xffffffffu, mx, 2));

            float z = 0.f;
            for (int kp = part; kp < 98; kp += 4) {
                __half2 hv = *reinterpret_cast<__half2*>(&Prow[kp]);
                float2 f = __half22float2(hv);
                float e0 = __expf(f.x - mx);
                float e1 = __expf(f.y - mx);
                z += e0 + e1;
                Prow[kp] = h2_u32(e0, e1);
            }
            z += __shfl_xor_sync(0xffffffffu, z, 1);
            z += __shfl_xor_sync(0xffffffffu, z, 2);
            if (part == 0) rowZ[rrow] = z;
            for (int kp = 98 + part; kp < KPJ; kp += 4) Prow[kp] = 0u;
        }
        __syncthreads();

        // ---- PV
        {
            float o[4][4];
#pragma unroll
            for (int nt = 0; nt < 4; nt++)
#pragma unroll
                for (int l = 0; l < 4; l++) o[nt][l] = 0.f;

#pragma unroll
            for (int ks = 0; ks < 13; ks++) {
                unsigned int af[4], bf[4][2];
                ldsm_x4(af, ps_base + 4u * ((wm + rsel) * PS + ks * 8 + csel));
#pragma unroll
                for (int nt = 0; nt < 4; nt++) {
                    int nb = wnO + nt * 8 + g;
                    bf[nt][0] = Vsm[(ks * 8 + t    ) * VS2 + nb];
                    bf[nt][1] = Vsm[(ks * 8 + t + 4) * VS2 + nb];
                }
#pragma unroll
                for (int nt = 0; nt < 4; nt++)
                    mma_f16(o[nt], af, bf[nt]);
            }
            int r0 = wm + g, r1 = wm + g + 8;
            float rz0 = 1.f / rowZ[r0], rz1 = 1.f / rowZ[r1];
#pragma unroll
            for (int nt = 0; nt < 4; nt++) {
                int d0 = wnO + nt * 8 + 2 * t;
                Rsm[r0 * RS + d0]     += o[nt][0] * rz0;
                Rsm[r0 * RS + d0 + 1] += o[nt][1] * rz0;
                Rsm[r1 * RS + d0]     += o[nt][2] * rz1;
                Rsm[r1 * RS + d0 + 1] += o[nt][3] * rz1;
            }
        }
        __syncthreads();

        // ---- LayerNorm + spatial-mean accumulation (register acc)
        for (int r = wid; r < len; r += 8) {
            float x0 = Rsm[r * RS + lane], x1 = Rsm[r * RS + lane + 32];
            float sum = x0 + x1, sq = x0 * x0 + x1 * x1;
#pragma unroll
            for (int o2 = 16; o2 > 0; o2 >>= 1) {
                sum += __shfl_xor_sync(0xffffffffu, sum, o2);
                sq  += __shfl_xor_sync(0xffffffffu, sq, o2);
            }
            float mean = sum * (1.f / 64.f);
            float var  = fmaxf(sq * (1.f / 64.f) - mean * mean, 0.f);
            float rs   = 1.f / (sqrtf(var) + EPS);
            acc0 += (x0 - mean) * rs * lg0 + lb0;
            acc1 += (x1 - mean) * rs * lg1 + lb1;
        }
    }

    __syncthreads();
    float* red = (float*)Psm;
    red[wid * 64 + lane]      = acc0;
    red[wid * 64 + lane + 32] = acc1;
    __syncthreads();
    if (tid < 64) {
        float s = 0.f;
#pragma unroll
        for (int w2 = 0; w2 < 8; w2++) s += red[w2 * 64 + tid];
        out[((size_t)b * HEADS + h) * DH + tid] = s * (1.f / 784.f);
    }
}

// ---------------------------------------------------------------------------
extern "C" void kernel_launch(void* const* d_in, const int* in_sizes, int n_in,
                              void* d_out, int out_size)
{
    const float* x      = (const float*)d_in[0];
    const float* w_dwq  = (const float*)d_in[1];
    const float* w_pwq  = (const float*)d_in[2];
    const float* w_dwkv = (const float*)d_in[3];
    const float* w_pwkv = (const float*)d_in[4];
    const float* w_ds   = (const float*)d_in[5];
    const float* ln_g   = (const float*)d_in[6];
    const float* ln_b   = (const float*)d_in[7];
    const float* bnq_g  = (const float*)d_in[8];
    const float* bnq_b  = (const float*)d_in[9];
    const float* bnq_m  = (const float*)d_in[10];
    const float* bnq_v  = (const float*)d_in[11];
    const float* bnkv_g = (const float*)d_in[12];
    const float* bnkv_b = (const float*)d_in[13];
    const float* bnkv_m = (const float*)d_in[14];
    const float* bnkv_v = (const float*)d_in[15];
    const float* bnds_g = (const float*)d_in[16];
    const float* bnds_b = (const float*)d_in[17];
    const float* bnds_m = (const float*)d_in[18];
    const float* bnds_v = (const float*)d_in[19];
    float* out = (float*)d_out;

    void *p_dqh, *p_dkvh, *p_xh, *p_wqh, *p_wkvh, *p_wdsh, *p_q, *p_kv, *p_res;
    cudaGetSymbolAddress(&p_dqh,  g_dqh);
    cudaGetSymbolAddress(&p_dkvh, g_dkvh);
    cudaGetSymbolAddress(&p_xh,   g_xh);
    cudaGetSymbolAddress(&p_wqh,  g_wqh);
    cudaGetSymbolAddress(&p_wkvh, g_wkvh);
    cudaGetSymbolAddress(&p_wdsh, g_wdsh);
    cudaGetSymbolAddress(&p_q,    g_q);
    cudaGetSymbolAddress(&p_kv,   g_kv);
    cudaGetSymbolAddress(&p_res,  g_res);

    const size_t gemm_smem = (size_t)STAGES * (ASTG + BSTG) * sizeof(uint32_t);
    cudaFuncSetAttribute(gemm_f16_kernel,
                         cudaFuncAttributeMaxDynamicSharedMemorySize, (int)gemm_smem);

    { int n = INNER * KU; pack_w_kernel<<<(n + 255) / 256, 256>>>(w_pwq, (uint32_t*)p_wqh, n); }
    dwconv_smem_kernel<<<NB * KU, 256>>>(
        x, w_dwq, bnq_g, bnq_b, bnq_m, bnq_v, (uint32_t*)p_dqh, 1, HH, WW);
    { int n = 2 * INNER * KU; pack_w_kernel<<<(n + 255) / 256, 256>>>(w_pwkv, (uint32_t*)p_wkvh, n); }
    {
        dim3 grid((S1 + 127) / 128, INNER / 128, NB);
        gemm_f16_kernel<<<grid, 256, gemm_smem>>>(
            (const uint32_t*)p_wqh, (const uint32_t*)p_dqh, (float*)p_q,
            INNER, S1, nullptr, nullptr, nullptr, nullptr);
    }
    dwconv_smem_kernel<<<NB * KU, 256>>>(
        x, w_dwkv, bnkv_g, bnkv_b, bnkv_m, bnkv_v, (uint32_t*)p_dkvh, 2, 14, 14);
    { int n = DH * KU; pack_w_kernel<<<(n + 255) / 256, 256>>>(w_ds, (uint32_t*)p_wdsh, n); }
    { int t2 = NB * KU * (S1 / 2); pack_x_kernel<<<(t2 + 255) / 256, 256>>>(x, (uint32_t*)p_xh, t2); }
    {
        dim3 grid((S2 + 127) / 128, (2 * INNER) / 128, NB);
        gemm_f16_kernel<<<grid, 256, gemm_smem>>>(
            (const uint32_t*)p_wkvh, (const uint32_t*)p_dkvh, (float*)p_kv,
            2 * INNER, S2, nullptr, nullptr, nullptr, nullptr);
    }
    {
        dim3 grid((S1 + 127) / 128, 1, NB);
        gemm_f16_kernel<<<grid, 256, gemm_smem>>>(
            (const uint32_t*)p_wdsh, (const uint32_t*)p_xh, (float*)p_res,
            DH, S1, bnds_g, bnds_b, bnds_m, bnds_v);
    }
    {
        size_t smem = (size_t)(64 * QS2 + 32 * KS2 + KPJ * VS2 + 64 * PS +
                               64 * RS + 64) * 4;
        cudaFuncSetAttribute(attn_f16_kernel,
                             cudaFuncAttributeMaxDynamicSharedMemorySize, (int)smem);
        attn_f16_kernel<<<NB * HEADS, 256, smem>>>(
            (const float*)p_q, (const float*)p_kv, (const float*)p_res,
            ln_g, ln_b, out);
    }
}